// round 10
// baseline (speedup 1.0000x reference)
#include <cuda_runtime.h>
#include <cuda_fp16.h>
#include <cstdint>
#include <cstddef>

// ---------------- problem constants ----------------
#define NBATCH 2
#define LSEQ   2048
#define DIM    1024
#define NH     16
#define DH     64
#define CHK    128
#define NCHK   (LSEQ / CHK)      // 16
#define MROWS  (NBATCH * LSEQ)   // 4096

// ---------------- device scratch (no allocs allowed) ----------------
__device__ __align__(16) float g_Q[MROWS * DIM];
__device__ __align__(16) float g_K[MROWS * DIM];
__device__ __align__(16) float g_V[MROWS * DIM];
__device__ __align__(16) float g_P[NBATCH * NH * NCHK * DH * DH];
__device__ __align__(16) __half g_Xhi[2][MROWS * DIM];   // 0=query 1=key
__device__ __align__(16) __half g_Xlo[2][MROWS * DIM];
__device__ __align__(16) __half g_Wh[3][DIM * DIM];      // Wq,Wk,Wv (single fp16)

// ---------------- small helpers ----------------
__device__ __forceinline__ uint32_t smem_u32(const void* p) {
    uint32_t a;
    asm("{ .reg .u64 t; cvta.to.shared.u64 t, %1; cvt.u32.u64 %0, t; }" : "=r"(a) : "l"(p));
    return a;
}
__device__ __forceinline__ void cp16(uint32_t s, const void* g) {
    asm volatile("cp.async.cg.shared.global [%0], [%1], 16;" :: "r"(s), "l"(g));
}
#define CP_COMMIT() asm volatile("cp.async.commit_group;" ::: "memory")
#define CP_WAIT1()  asm volatile("cp.async.wait_group 1;" ::: "memory")

__device__ __forceinline__ void mma16816h(float* c, const uint32_t* a, const uint32_t* b) {
    asm volatile(
        "mma.sync.aligned.m16n8k16.row.col.f32.f16.f16.f32 "
        "{%0,%1,%2,%3}, {%4,%5,%6,%7}, {%8,%9}, {%0,%1,%2,%3};"
        : "+f"(c[0]), "+f"(c[1]), "+f"(c[2]), "+f"(c[3])
        : "r"(a[0]), "r"(a[1]), "r"(a[2]), "r"(a[3]), "r"(b[0]), "r"(b[1]));
}
__device__ __forceinline__ void ldsm4(uint32_t* r, uint32_t addr) {
    asm volatile("ldmatrix.sync.aligned.m8n8.x4.shared.b16 {%0,%1,%2,%3}, [%4];"
                 : "=r"(r[0]), "=r"(r[1]), "=r"(r[2]), "=r"(r[3]) : "r"(addr));
}

// ---------------- fp16 split conversion ----------------
// X (query/key): hi/lo fp16 split. W: single fp16.
__global__ __launch_bounds__(256)
void conv_split(const float* __restrict__ q, const float* __restrict__ k,
                const float* __restrict__ wq, const float* __restrict__ wk,
                const float* __restrict__ wv)
{
    int y = blockIdx.y;
    if (y < 2) {
        const float* src = y ? k : q;
        __half* hi = g_Xhi[y];
        __half* lo = g_Xlo[y];
        int n4 = (MROWS * DIM) >> 2;
        for (int i = blockIdx.x * blockDim.x + threadIdx.x; i < n4;
             i += gridDim.x * blockDim.x) {
            float4 f = ((const float4*)src)[i];
            __half h0 = __float2half(f.x);
            __half h1 = __float2half(f.y);
            __half h2 = __float2half(f.z);
            __half h3 = __float2half(f.w);
            __half l0 = __float2half(f.x - __half2float(h0));
            __half l1 = __float2half(f.y - __half2float(h1));
            __half l2 = __float2half(f.z - __half2float(h2));
            __half l3 = __float2half(f.w - __half2float(h3));
            ushort4 uh = make_ushort4(__half_as_ushort(h0), __half_as_ushort(h1),
                                      __half_as_ushort(h2), __half_as_ushort(h3));
            ushort4 ul = make_ushort4(__half_as_ushort(l0), __half_as_ushort(l1),
                                      __half_as_ushort(l2), __half_as_ushort(l3));
            ((ushort4*)hi)[i] = uh;
            ((ushort4*)lo)[i] = ul;
        }
    } else {
        const float* src = (y == 2) ? wq : (y == 3) ? wk : wv;
        __half* dst = g_Wh[y - 2];
        int n4 = (DIM * DIM) >> 2;
        for (int i = blockIdx.x * blockDim.x + threadIdx.x; i < n4;
             i += gridDim.x * blockDim.x) {
            float4 f = ((const float4*)src)[i];
            ushort4 u = make_ushort4(
                __half_as_ushort(__float2half(f.x)), __half_as_ushort(__float2half(f.y)),
                __half_as_ushort(__float2half(f.z)), __half_as_ushort(__float2half(f.w)));
            ((ushort4*)dst)[i] = u;
        }
    }
}

// ---------------- HMMA projection GEMM (+ fused per-head softmax) ----------------
// Out[m,n] = sum_k X[m,k]*W[n,k], as Ahi*W + Alo*W  (2 fp16 passes, fp32 accum).
// 128x128 CTA tile, BK=64 halves (32 iters = 2 passes x 16), 8 warps of 64x32,
// ldmatrix.x4, XOR-swizzled 128B rows, 3-stage cp.async ring.
// Epilogue (z<2): per-head softmax via smem reduction.
#define STAGE_BYTES 32768
#define SMEM_TOTAL  (3 * STAGE_BYTES)     // 96 KB

__device__ __forceinline__ uint32_t swz(int row, int c) {
    return (uint32_t)(row * 128 + ((c ^ (row & 7)) << 4));
}

__global__ __launch_bounds__(256, 2)
void proj_hmma()
{
    extern __shared__ char smem[];
    const uint32_t sb = smem_u32(smem);

    const int tid = threadIdx.x;
    const int wid = tid >> 5;
    const int lane = tid & 31;
    const int wm = wid >> 2;       // 0..1
    const int wn = wid & 3;        // 0..3
    const int z = blockIdx.z;

    const __half* __restrict__ Ahi = g_Xhi[z ? 1 : 0];
    const __half* __restrict__ Alo = g_Xlo[z ? 1 : 0];
    const __half* __restrict__ Bw  = g_Wh[z];
    float* __restrict__ Out = (z == 0) ? g_Q : (z == 1) ? g_K : g_V;

    const int m0 = blockIdx.y * 128;
    const int n0 = blockIdx.x * 128;

    float acc[4][4][4];
#pragma unroll
    for (int i = 0; i < 4; i++)
#pragma unroll
        for (int j = 0; j < 4; j++)
#pragma unroll
            for (int r = 0; r < 4; r++) acc[i][j][r] = 0.f;

    const int lrow = tid >> 1;
    const int lc4  = (tid & 1) * 4;
    auto load_tile = [&](int kk, int stg) {
        const int pass = kk >> 4;
        const int k0 = (kk & 15) * 64;
        const __half* A = pass ? Alo : Ahi;
        const uint32_t sa = sb + stg * STAGE_BYTES;
        const uint32_t sbB = sa + 16384;
        const __half* ga = A + (size_t)(m0 + lrow) * DIM + k0 + lc4 * 8;
        const __half* gb = Bw + (size_t)(n0 + lrow) * DIM + k0 + lc4 * 8;
#pragma unroll
        for (int c = 0; c < 4; c++) {
            cp16(sa  + swz(lrow, lc4 + c), ga + c * 8);
            cp16(sbB + swz(lrow, lc4 + c), gb + c * 8);
        }
    };

    const int a_row = (lane & 7) + ((lane >> 3) & 1) * 8;
    const int a_cofs = lane >> 4;
    const int b_row0 = ((lane >> 4) & 1) * 8 + (lane & 7);
    const int b_cofs = (lane >> 3) & 1;

    load_tile(0, 0); CP_COMMIT();
    load_tile(1, 1); CP_COMMIT();

    for (int kk = 0; kk < 32; kk++) {
        const int stg = kk % 3;
        CP_WAIT1();
        __syncthreads();
        if (kk + 2 < 32) { load_tile(kk + 2, (kk + 2) % 3); CP_COMMIT(); }

        const uint32_t sa = sb + stg * STAGE_BYTES;
        const uint32_t sbB = sa + 16384;

#pragma unroll
        for (int ks = 0; ks < 4; ks++) {
            const int c0 = ks * 2;
            uint32_t a[4][4], b[8];
#pragma unroll
            for (int i = 0; i < 4; i++) {
                const int r0 = wm * 64 + i * 16;
                ldsm4(a[i], sa + swz(r0 + a_row, c0 + a_cofs));
            }
#pragma unroll
            for (int jp = 0; jp < 2; jp++) {
                const int c0b = wn * 32 + jp * 16;
                ldsm4(&b[jp * 4], sbB + swz(c0b + b_row0, c0 + b_cofs));
            }
#pragma unroll
            for (int i = 0; i < 4; i++)
#pragma unroll
                for (int j = 0; j < 4; j++)
                    mma16816h(acc[i][j], a[i], &b[j * 2]);
        }
    }

    // ---------------- epilogue ----------------
    const int g = lane >> 2;
    const int tg = lane & 3;
    __syncthreads();

    if (z < 2) {
        float* red = (float*)smem;   // [128 rows][2 seg][2 pair]
        const int seg = wn >> 1;
        const int pr = wn & 1;

        float ml[4][2];
#pragma unroll
        for (int i = 0; i < 4; i++)
#pragma unroll
            for (int h = 0; h < 2; h++) {
                float m = acc[i][0][h * 2];
#pragma unroll
                for (int j = 0; j < 4; j++) {
                    m = fmaxf(m, acc[i][j][h * 2]);
                    m = fmaxf(m, acc[i][j][h * 2 + 1]);
                }
                m = fmaxf(m, __shfl_xor_sync(0xffffffffu, m, 1));
                m = fmaxf(m, __shfl_xor_sync(0xffffffffu, m, 2));
                ml[i][h] = m;
            }
        if (tg == 0) {
#pragma unroll
            for (int i = 0; i < 4; i++)
#pragma unroll
                for (int h = 0; h < 2; h++) {
                    int row = wm * 64 + i * 16 + h * 8 + g;
                    red[(row * 2 + seg) * 2 + pr] = ml[i][h];
                }
        }
        __syncthreads();
        float mseg[4][2];
#pragma unroll
        for (int i = 0; i < 4; i++)
#pragma unroll
            for (int h = 0; h < 2; h++) {
                int row = wm * 64 + i * 16 + h * 8 + g;
                mseg[i][h] = fmaxf(red[(row * 2 + seg) * 2 + 0],
                                   red[(row * 2 + seg) * 2 + 1]);
            }
        __syncthreads();

        float sl[4][2];
#pragma unroll
        for (int i = 0; i < 4; i++)
#pragma unroll
            for (int h = 0; h < 2; h++) {
                float s = 0.f;
#pragma unroll
                for (int j = 0; j < 4; j++) {
                    float e0 = __expf(acc[i][j][h * 2]     - mseg[i][h]);
                    float e1 = __expf(acc[i][j][h * 2 + 1] - mseg[i][h]);
                    acc[i][j][h * 2] = e0; acc[i][j][h * 2 + 1] = e1;
                    s += e0 + e1;
                }
                s += __shfl_xor_sync(0xffffffffu, s, 1);
                s += __shfl_xor_sync(0xffffffffu, s, 2);
                sl[i][h] = s;
            }
        if (tg == 0) {
#pragma unroll
            for (int i = 0; i < 4; i++)
#pragma unroll
                for (int h = 0; h < 2; h++) {
                    int row = wm * 64 + i * 16 + h * 8 + g;
                    red[(row * 2 + seg) * 2 + pr] = sl[i][h];
                }
        }
        __syncthreads();
#pragma unroll
        for (int i = 0; i < 4; i++)
#pragma unroll
            for (int h = 0; h < 2; h++) {
                int row = wm * 64 + i * 16 + h * 8 + g;
                float inv = 1.0f / (red[(row * 2 + seg) * 2 + 0] +
                                    red[(row * 2 + seg) * 2 + 1]);
#pragma unroll
                for (int j = 0; j < 4; j++) {
                    acc[i][j][h * 2]     *= inv;
                    acc[i][j][h * 2 + 1] *= inv;
                }
            }
    }

#pragma unroll
    for (int i = 0; i < 4; i++) {
        const int r0 = m0 + wm * 64 + i * 16 + g;
#pragma unroll
        for (int j = 0; j < 4; j++) {
            const int cc = n0 + wn * 32 + j * 8 + tg * 2;
            *(float2*)&Out[(size_t)r0 * DIM + cc] = make_float2(acc[i][j][0], acc[i][j][1]);
            *(float2*)&Out[(size_t)(r0 + 8) * DIM + cc] = make_float2(acc[i][j][2], acc[i][j][3]);
        }
    }
}

// ---------------- per-chunk KV outer-product sums ----------------
__global__ __launch_bounds__(256)
void chunk_kv()
{
    extern __shared__ float sm[];
    float* ks = sm;          // 128*64
    float* vs = sm + 8192;   // 128*64

    const int c = blockIdx.x;
    const int nh = blockIdx.y;
    const int n = nh >> 4, h = nh & 15;
    const int t0 = c * CHK;
    const size_t base = ((size_t)(n * LSEQ + t0)) * DIM + h * DH;

    for (int idx = threadIdx.x; idx < CHK * DH; idx += 256) {
        int row = idx >> 6, col = idx & 63;
        ks[idx] = g_K[base + (size_t)row * DIM + col];
        vs[idx] = g_V[base + (size_t)row * DIM + col];
    }
    __syncthreads();

    const int tx = threadIdx.x & 15;
    const int ty = threadIdx.x >> 4;
    float acc[4][4];
#pragma unroll
    for (int i = 0; i < 4; i++)
#pragma unroll
        for (int j = 0; j < 4; j++) acc[i][j] = 0.f;

    for (int t = 0; t < CHK; t += 2) {
        float4 a0 = *(const float4*)&ks[t * 64 + ty * 4];
        float4 b0 = *(const float4*)&vs[t * 64 + tx * 4];
        float4 a1 = *(const float4*)&ks[(t + 1) * 64 + ty * 4];
        float4 b1 = *(const float4*)&vs[(t + 1) * 64 + tx * 4];
        const float a0v[4] = {a0.x, a0.y, a0.z, a0.w};
        const float b0v[4] = {b0.x, b0.y, b0.z, b0.w};
        const float a1v[4] = {a1.x, a1.y, a1.z, a1.w};
        const float b1v[4] = {b1.x, b1.y, b1.z, b1.w};
#pragma unroll
        for (int i = 0; i < 4; i++)
#pragma unroll
            for (int j = 0; j < 4; j++)
                acc[i][j] = fmaf(a0v[i], b0v[j], acc[i][j]);
#pragma unroll
        for (int i = 0; i < 4; i++)
#pragma unroll
            for (int j = 0; j < 4; j++)
                acc[i][j] = fmaf(a1v[i], b1v[j], acc[i][j]);
    }

    float* P = g_P + ((size_t)nh * NCHK + c) * (DH * DH);
#pragma unroll
    for (int i = 0; i < 4; i++)
#pragma unroll
        for (int j = 0; j < 4; j++)
            P[(ty * 4 + i) * 64 + tx * 4 + j] = acc[i][j];
}

// ---------------- exclusive prefix over chunks ----------------
__global__ __launch_bounds__(512)
void prefix_kv()
{
    const int nh = blockIdx.x >> 3;
    const int slab = blockIdx.x & 7;
    float* P = g_P + (size_t)nh * NCHK * (DH * DH);
    const int idx = slab * 512 + threadIdx.x;
    float run = 0.f;
#pragma unroll
    for (int c = 0; c < NCHK; c++) {
        float t = P[c * (DH * DH) + idx];
        P[c * (DH * DH) + idx] = run;
        run += t;
    }
}

// ---------------- attention output (112.5 KB smem -> 2 CTA/SM) ----------------
#define QSP 65
#define AO_QS    0
#define AO_AM    (128 * QSP)               // 8320 floats
#define AO_AUX   (AO_AM + 128 * 128)       // 24704 floats
#define AO_FLTS  (AO_AUX + 4096)           // 28800 floats
#define AO_BYTES (AO_FLTS * 4)             // 115200 bytes

__global__ __launch_bounds__(256, 2)
void attn_out(float* __restrict__ out)
{
    extern __shared__ float sm[];
    float* qs  = sm + AO_QS;    // 128 x 65
    float* Am  = sm + AO_AM;    // 128 x 128
    float* aux = sm + AO_AUX;   // 64 x 64 (kT half / Ss)

    const int c = blockIdx.x;
    const int nh = blockIdx.y;
    const int n = nh >> 4, h = nh & 15;
    const int t0 = c * CHK;
    const size_t base = ((size_t)(n * LSEQ + t0)) * DIM + h * DH;
    const int tid = threadIdx.x;
    const int lane = tid & 31;
    const int wid = tid >> 5;
    const int tx = tid & 15;
    const int ty = tid >> 4;

    for (int idx = tid; idx < CHK * DH; idx += 256) {
        int row = idx >> 6, col = idx & 63;
        qs[row * QSP + col] = g_Q[base + (size_t)row * DIM + col];
    }
    for (int idx = tid; idx < 64 * 64; idx += 256) {
        int s = idx >> 6, d = idx & 63;
        aux[d * 64 + s] = g_K[base + (size_t)s * DIM + d];
    }
    __syncthreads();

    // stage 1a: Am[:, 0:64] = causal(q @ kT0)
    {
        const int rr0 = wid * 16 + (lane >> 3) * 4;
        const int ss0 = (lane & 7) * 8;
        float acc[4][8];
#pragma unroll
        for (int i = 0; i < 4; i++)
#pragma unroll
            for (int j = 0; j < 8; j++) acc[i][j] = 0.f;
        for (int d = 0; d < DH; d++) {
            float a[4], b[8];
#pragma unroll
            for (int i = 0; i < 4; i++) a[i] = qs[(rr0 + i) * QSP + d];
#pragma unroll
            for (int j = 0; j < 8; j++) b[j] = aux[d * 64 + ss0 + j];
#pragma unroll
            for (int i = 0; i < 4; i++)
#pragma unroll
                for (int j = 0; j < 8; j++)
                    acc[i][j] = fmaf(a[i], b[j], acc[i][j]);
        }
#pragma unroll
        for (int i = 0; i < 4; i++) {
            int r = rr0 + i;
#pragma unroll
            for (int j = 0; j < 8; j++) {
                int s = ss0 + j;
                Am[r * CHK + s] = (s <= r) ? acc[i][j] : 0.f;
            }
        }
    }
    __syncthreads();

    for (int idx = tid; idx < 64 * 64; idx += 256) {
        int s = idx >> 6, d = idx & 63;
        aux[d * 64 + s] = g_K[base + (size_t)(64 + s) * DIM + d];
    }
    __syncthreads();

    // stage 1b: Am[64:128, 64:128] = causal(q @ kT1); zero Am[0:64, 64:128]
    {
        const int rr0 = 64 + wid * 8 + (lane >> 3) * 2;
        const int ss0 = 64 + (lane & 7) * 8;
        float acc[2][8];
#pragma unroll
        for (int i = 0; i < 2; i++)
#pragma unroll
            for (int j = 0; j < 8; j++) acc[i][j] = 0.f;
        for (int d = 0; d < DH; d++) {
            float a[2], b[8];
#pragma unroll
            for (int i = 0; i < 2; i++) a[i] = qs[(rr0 + i) * QSP + d];
#pragma unroll
            for (int j = 0; j < 8; j++) b[j] = aux[d * 64 + (ss0 - 64) + j];
#pragma unroll
            for (int i = 0; i < 2; i++)
#pragma unroll
                for (int j = 0; j < 8; j++)
                    acc[i][j] = fmaf(a[i], b[j], acc[i][j]);
        }
#pragma unroll
        for (int i = 0; i < 2; i++) {
            int r = rr0 + i;
#pragma unroll
            for (int j = 0; j < 8; j++) {
                int s = ss0 + j;
                Am[r * CHK + s] = (s <= r) ? acc[i][j] : 0.f;
            }
        }
        for (int idx = tid; idx < 64 * 64; idx += 256) {
            int r = idx >> 6, s2 = idx & 63;
            Am[r * CHK + 64 + s2] = 0.f;
        }
    }
    __syncthreads();

    {
        const float* Pp = g_P + ((size_t)nh * NCHK + c) * (DH * DH);
        for (int idx = tid; idx < DH * DH; idx += 256) aux[idx] = Pp[idx];
    }
    __syncthreads();

    float o[8][4];
#pragma unroll
    for (int i = 0; i < 8; i++)
#pragma unroll
        for (int j = 0; j < 4; j++) o[i][j] = 0.f;

    for (int d = 0; d < DH; d++) {
        float a[8], b[4];
#pragma unroll
        for (int i = 0; i < 8; i++) a[i] = qs[(ty * 8 + i) * QSP + d];
#pragma unroll
        for (int j = 0; j < 4; j++) b[j] = aux[d * 64 + tx * 4 + j];
#pragma unroll
        for (int i = 0; i < 8; i++)
#pragma unroll
            for (int j = 0; j < 4; j++)
                o[i][j] = fmaf(a[i], b[j], o[i][j]);
    }
    __syncthreads();

    float* vs = sm + AO_QS;
    for (int idx = tid; idx < CHK * DH; idx += 256) {
        int row = idx >> 6, col = idx & 63;
        vs[idx] = g_V[base + (size_t)row * DIM + col];
    }
    __syncthreads();

    const int sHi = (wid + 1) * 16;
    for (int s = 0; s < sHi; s++) {
        float a[8], b[4];
#pragma unroll
        for (int i = 0; i < 8; i++) a[i] = Am[(ty * 8 + i) * CHK + s];
#pragma unroll
        for (int j = 0; j < 4; j++) b[j] = vs[s * 64 + tx * 4 + j];
#pragma unroll
        for (int i = 0; i < 8; i++)
#pragma unroll
            for (int j = 0; j < 4; j++)
                o[i][j] = fmaf(a[i], b[j], o[i][j]);
    }

#pragma unroll
    for (int i = 0; i < 8; i++) {
        int r = ty * 8 + i;
#pragma unroll
        for (int j = 0; j < 4; j++)
            out[base + (size_t)r * DIM + tx * 4 + j] = o[i][j];
    }
}

// ---------------------------------------------------------------------------
extern "C" void kernel_launch(void* const* d_in, const int* in_sizes, int n_in,
                              void* d_out, int out_size)
{
    const float* query = (const float*)d_in[0];
    const float* key   = (const float*)d_in[1];
    const float* Wq    = (const float*)d_in[2];
    const float* Wk    = (const float*)d_in[3];
    const float* Wv    = (const float*)d_in[4];
    float* out = (float*)d_out;

    cudaFuncSetAttribute(proj_hmma, cudaFuncAttributeMaxDynamicSharedMemorySize, SMEM_TOTAL);
    cudaFuncSetAttribute(chunk_kv, cudaFuncAttributeMaxDynamicSharedMemorySize, 65536);
    cudaFuncSetAttribute(attn_out, cudaFuncAttributeMaxDynamicSharedMemorySize, AO_BYTES);

    // 1. fp16 conversion: X hi/lo split, W single
    conv_split<<<dim3(256, 5), 256>>>(query, key, Wq, Wk, Wv);

    // 2. projections on fp16 HMMA (2 passes) with fused per-head softmax
    proj_hmma<<<dim3(8, 32, 3), 256, SMEM_TOTAL>>>();

    // 3. chunked causal linear attention
    dim3 agrid(NCHK, NBATCH * NH);
    chunk_kv<<<agrid, 256, 65536>>>();
    prefix_kv<<<NBATCH * NH * 8, 512>>>();
    attn_out<<<agrid, 256, AO_BYTES>>>(out);
}

// round 11
// speedup vs baseline: 1.5175x; 1.5175x over previous
#include <cuda_runtime.h>
#include <cuda_fp16.h>
#include <cstdint>
#include <cstddef>

// ---------------- problem constants ----------------
#define NBATCH 2
#define LSEQ   2048
#define DIM    1024
#define NH     16
#define DH     64
#define CHK    128
#define NCHK   (LSEQ / CHK)      // 16
#define MROWS  (NBATCH * LSEQ)   // 4096

// lo-pass exact rescale (power of 2): Alo stored x16, Wl stored /16
#define LO_SCALE 16.0f
#define LO_INV   0.0625f

// ---------------- device scratch (no allocs allowed) ----------------
__device__ __align__(16) float g_Q[MROWS * DIM];
__device__ __align__(16) float g_K[MROWS * DIM];
__device__ __align__(16) float g_V[MROWS * DIM];
__device__ __align__(16) float g_P[NBATCH * NH * NCHK * DH * DH];
__device__ __align__(16) __half g_Xhi[2][MROWS * DIM];   // 0=query 1=key
__device__ __align__(16) __half g_Xlo[2][MROWS * DIM];   // residual x16
__device__ __align__(16) __half g_Wh[3][DIM * DIM];      // W fp16
__device__ __align__(16) __half g_Wl[3][DIM * DIM];      // W/16 fp16

// ---------------- small helpers ----------------
__device__ __forceinline__ uint32_t smem_u32(const void* p) {
    uint32_t a;
    asm("{ .reg .u64 t; cvta.to.shared.u64 t, %1; cvt.u32.u64 %0, t; }" : "=r"(a) : "l"(p));
    return a;
}
__device__ __forceinline__ void cp16(uint32_t s, const void* g) {
    asm volatile("cp.async.cg.shared.global [%0], [%1], 16;" :: "r"(s), "l"(g));
}
#define CP_COMMIT() asm volatile("cp.async.commit_group;" ::: "memory")
#define CP_WAIT1()  asm volatile("cp.async.wait_group 1;" ::: "memory")

__device__ __forceinline__ void mma16816h(float* c, const uint32_t* a, const uint32_t* b) {
    asm volatile(
        "mma.sync.aligned.m16n8k16.row.col.f32.f16.f16.f32 "
        "{%0,%1,%2,%3}, {%4,%5,%6,%7}, {%8,%9}, {%0,%1,%2,%3};"
        : "+f"(c[0]), "+f"(c[1]), "+f"(c[2]), "+f"(c[3])
        : "r"(a[0]), "r"(a[1]), "r"(a[2]), "r"(a[3]), "r"(b[0]), "r"(b[1]));
}
__device__ __forceinline__ void ldsm4(uint32_t* r, uint32_t addr) {
    asm volatile("ldmatrix.sync.aligned.m8n8.x4.shared.b16 {%0,%1,%2,%3}, [%4];"
                 : "=r"(r[0]), "=r"(r[1]), "=r"(r[2]), "=r"(r[3]) : "r"(addr));
}

// ---------------- fp16 conversion ----------------
// X: hi + scaled-lo split. W: fp16 and fp16/16 copies.
__global__ __launch_bounds__(256)
void conv_split(const float* __restrict__ q, const float* __restrict__ k,
                const float* __restrict__ wq, const float* __restrict__ wk,
                const float* __restrict__ wv)
{
    int y = blockIdx.y;
    if (y < 2) {
        const float* src = y ? k : q;
        __half* hi = g_Xhi[y];
        __half* lo = g_Xlo[y];
        int n4 = (MROWS * DIM) >> 2;
        for (int i = blockIdx.x * blockDim.x + threadIdx.x; i < n4;
             i += gridDim.x * blockDim.x) {
            float4 f = ((const float4*)src)[i];
            __half h0 = __float2half(f.x);
            __half h1 = __float2half(f.y);
            __half h2 = __float2half(f.z);
            __half h3 = __float2half(f.w);
            __half l0 = __float2half((f.x - __half2float(h0)) * LO_SCALE);
            __half l1 = __float2half((f.y - __half2float(h1)) * LO_SCALE);
            __half l2 = __float2half((f.z - __half2float(h2)) * LO_SCALE);
            __half l3 = __float2half((f.w - __half2float(h3)) * LO_SCALE);
            ushort4 uh = make_ushort4(__half_as_ushort(h0), __half_as_ushort(h1),
                                      __half_as_ushort(h2), __half_as_ushort(h3));
            ushort4 ul = make_ushort4(__half_as_ushort(l0), __half_as_ushort(l1),
                                      __half_as_ushort(l2), __half_as_ushort(l3));
            ((ushort4*)hi)[i] = uh;
            ((ushort4*)lo)[i] = ul;
        }
    } else {
        const float* src = (y == 2) ? wq : (y == 3) ? wk : wv;
        __half* dh = g_Wh[y - 2];
        __half* dl = g_Wl[y - 2];
        int n4 = (DIM * DIM) >> 2;
        for (int i = blockIdx.x * blockDim.x + threadIdx.x; i < n4;
             i += gridDim.x * blockDim.x) {
            float4 f = ((const float4*)src)[i];
            ushort4 uh = make_ushort4(
                __half_as_ushort(__float2half(f.x)), __half_as_ushort(__float2half(f.y)),
                __half_as_ushort(__float2half(f.z)), __half_as_ushort(__float2half(f.w)));
            ushort4 ul = make_ushort4(
                __half_as_ushort(__float2half(f.x * LO_INV)),
                __half_as_ushort(__float2half(f.y * LO_INV)),
                __half_as_ushort(__float2half(f.z * LO_INV)),
                __half_as_ushort(__float2half(f.w * LO_INV)));
            ((ushort4*)dh)[i] = uh;
            ((ushort4*)dl)[i] = ul;
        }
    }
}

// ---------------- HMMA projection GEMM (+ fused per-head softmax) ----------------
// Out[m,n] = sum_k X[m,k]*W[n,k] = Ahi*Wh + (16*Alo)*(Wh/16)   (2 fp16 passes).
// 128x128 CTA tile, BK=64 halves (32 iters), 8 warps of 64x32, ldmatrix.x4,
// XOR-swizzled 128B rows, 3-stage cp.async ring.
#define STAGE_BYTES 32768
#define SMEM_TOTAL  (3 * STAGE_BYTES)     // 96 KB

__device__ __forceinline__ uint32_t swz(int row, int c) {
    return (uint32_t)(row * 128 + ((c ^ (row & 7)) << 4));
}

__global__ __launch_bounds__(256, 2)
void proj_hmma()
{
    extern __shared__ char smem[];
    const uint32_t sb = smem_u32(smem);

    const int tid = threadIdx.x;
    const int wid = tid >> 5;
    const int lane = tid & 31;
    const int wm = wid >> 2;       // 0..1
    const int wn = wid & 3;        // 0..3
    const int z = blockIdx.z;

    const __half* __restrict__ Ahi = g_Xhi[z ? 1 : 0];
    const __half* __restrict__ Alo = g_Xlo[z ? 1 : 0];
    const __half* __restrict__ Bh  = g_Wh[z];
    const __half* __restrict__ Bl  = g_Wl[z];
    float* __restrict__ Out = (z == 0) ? g_Q : (z == 1) ? g_K : g_V;

    const int m0 = blockIdx.y * 128;
    const int n0 = blockIdx.x * 128;

    float acc[4][4][4];
#pragma unroll
    for (int i = 0; i < 4; i++)
#pragma unroll
        for (int j = 0; j < 4; j++)
#pragma unroll
            for (int r = 0; r < 4; r++) acc[i][j][r] = 0.f;

    const int lrow = tid >> 1;
    const int lc4  = (tid & 1) * 4;
    auto load_tile = [&](int kk, int stg) {
        const int pass = kk >> 4;
        const int k0 = (kk & 15) * 64;
        const __half* A = pass ? Alo : Ahi;
        const __half* B = pass ? Bl  : Bh;
        const uint32_t sa = sb + stg * STAGE_BYTES;
        const uint32_t sbB = sa + 16384;
        const __half* ga = A + (size_t)(m0 + lrow) * DIM + k0 + lc4 * 8;
        const __half* gb = B + (size_t)(n0 + lrow) * DIM + k0 + lc4 * 8;
#pragma unroll
        for (int c = 0; c < 4; c++) {
            cp16(sa  + swz(lrow, lc4 + c), ga + c * 8);
            cp16(sbB + swz(lrow, lc4 + c), gb + c * 8);
        }
    };

    const int a_row = (lane & 7) + ((lane >> 3) & 1) * 8;
    const int a_cofs = lane >> 4;
    const int b_row0 = ((lane >> 4) & 1) * 8 + (lane & 7);
    const int b_cofs = (lane >> 3) & 1;

    load_tile(0, 0); CP_COMMIT();
    load_tile(1, 1); CP_COMMIT();

    for (int kk = 0; kk < 32; kk++) {
        const int stg = kk % 3;
        CP_WAIT1();
        __syncthreads();
        if (kk + 2 < 32) { load_tile(kk + 2, (kk + 2) % 3); CP_COMMIT(); }

        const uint32_t sa = sb + stg * STAGE_BYTES;
        const uint32_t sbB = sa + 16384;

#pragma unroll
        for (int ks = 0; ks < 4; ks++) {
            const int c0 = ks * 2;
            uint32_t a[4][4], b[8];
#pragma unroll
            for (int i = 0; i < 4; i++) {
                const int r0 = wm * 64 + i * 16;
                ldsm4(a[i], sa + swz(r0 + a_row, c0 + a_cofs));
            }
#pragma unroll
            for (int jp = 0; jp < 2; jp++) {
                const int c0b = wn * 32 + jp * 16;
                ldsm4(&b[jp * 4], sbB + swz(c0b + b_row0, c0 + b_cofs));
            }
#pragma unroll
            for (int i = 0; i < 4; i++)
#pragma unroll
                for (int j = 0; j < 4; j++)
                    mma16816h(acc[i][j], a[i], &b[j * 2]);
        }
    }

    // ---------------- epilogue ----------------
    const int g = lane >> 2;
    const int tg = lane & 3;
    __syncthreads();

    if (z < 2) {
        float* red = (float*)smem;   // [128 rows][2 seg][2 pair]
        const int seg = wn >> 1;
        const int pr = wn & 1;

        float ml[4][2];
#pragma unroll
        for (int i = 0; i < 4; i++)
#pragma unroll
            for (int h = 0; h < 2; h++) {
                float m = acc[i][0][h * 2];
#pragma unroll
                for (int j = 0; j < 4; j++) {
                    m = fmaxf(m, acc[i][j][h * 2]);
                    m = fmaxf(m, acc[i][j][h * 2 + 1]);
                }
                m = fmaxf(m, __shfl_xor_sync(0xffffffffu, m, 1));
                m = fmaxf(m, __shfl_xor_sync(0xffffffffu, m, 2));
                ml[i][h] = m;
            }
        if (tg == 0) {
#pragma unroll
            for (int i = 0; i < 4; i++)
#pragma unroll
                for (int h = 0; h < 2; h++) {
                    int row = wm * 64 + i * 16 + h * 8 + g;
                    red[(row * 2 + seg) * 2 + pr] = ml[i][h];
                }
        }
        __syncthreads();
        float mseg[4][2];
#pragma unroll
        for (int i = 0; i < 4; i++)
#pragma unroll
            for (int h = 0; h < 2; h++) {
                int row = wm * 64 + i * 16 + h * 8 + g;
                mseg[i][h] = fmaxf(red[(row * 2 + seg) * 2 + 0],
                                   red[(row * 2 + seg) * 2 + 1]);
            }
        __syncthreads();

        float sl[4][2];
#pragma unroll
        for (int i = 0; i < 4; i++)
#pragma unroll
            for (int h = 0; h < 2; h++) {
                float s = 0.f;
#pragma unroll
                for (int j = 0; j < 4; j++) {
                    float e0 = __expf(acc[i][j][h * 2]     - mseg[i][h]);
                    float e1 = __expf(acc[i][j][h * 2 + 1] - mseg[i][h]);
                    acc[i][j][h * 2] = e0; acc[i][j][h * 2 + 1] = e1;
                    s += e0 + e1;
                }
                s += __shfl_xor_sync(0xffffffffu, s, 1);
                s += __shfl_xor_sync(0xffffffffu, s, 2);
                sl[i][h] = s;
            }
        if (tg == 0) {
#pragma unroll
            for (int i = 0; i < 4; i++)
#pragma unroll
                for (int h = 0; h < 2; h++) {
                    int row = wm * 64 + i * 16 + h * 8 + g;
                    red[(row * 2 + seg) * 2 + pr] = sl[i][h];
                }
        }
        __syncthreads();
#pragma unroll
        for (int i = 0; i < 4; i++)
#pragma unroll
            for (int h = 0; h < 2; h++) {
                int row = wm * 64 + i * 16 + h * 8 + g;
                float inv = 1.0f / (red[(row * 2 + seg) * 2 + 0] +
                                    red[(row * 2 + seg) * 2 + 1]);
#pragma unroll
                for (int j = 0; j < 4; j++) {
                    acc[i][j][h * 2]     *= inv;
                    acc[i][j][h * 2 + 1] *= inv;
                }
            }
    }

#pragma unroll
    for (int i = 0; i < 4; i++) {
        const int r0 = m0 + wm * 64 + i * 16 + g;
#pragma unroll
        for (int j = 0; j < 4; j++) {
            const int cc = n0 + wn * 32 + j * 8 + tg * 2;
            *(float2*)&Out[(size_t)r0 * DIM + cc] = make_float2(acc[i][j][0], acc[i][j][1]);
            *(float2*)&Out[(size_t)(r0 + 8) * DIM + cc] = make_float2(acc[i][j][2], acc[i][j][3]);
        }
    }
}

// ---------------- per-chunk KV outer-product sums ----------------
__global__ __launch_bounds__(256)
void chunk_kv()
{
    extern __shared__ float sm[];
    float* ks = sm;          // 128*64
    float* vs = sm + 8192;   // 128*64

    const int c = blockIdx.x;
    const int nh = blockIdx.y;
    const int n = nh >> 4, h = nh & 15;
    const int t0 = c * CHK;
    const size_t base = ((size_t)(n * LSEQ + t0)) * DIM + h * DH;

    for (int idx = threadIdx.x; idx < CHK * DH; idx += 256) {
        int row = idx >> 6, col = idx & 63;
        ks[idx] = g_K[base + (size_t)row * DIM + col];
        vs[idx] = g_V[base + (size_t)row * DIM + col];
    }
    __syncthreads();

    const int tx = threadIdx.x & 15;
    const int ty = threadIdx.x >> 4;
    float acc[4][4];
#pragma unroll
    for (int i = 0; i < 4; i++)
#pragma unroll
        for (int j = 0; j < 4; j++) acc[i][j] = 0.f;

    for (int t = 0; t < CHK; t += 2) {
        float4 a0 = *(const float4*)&ks[t * 64 + ty * 4];
        float4 b0 = *(const float4*)&vs[t * 64 + tx * 4];
        float4 a1 = *(const float4*)&ks[(t + 1) * 64 + ty * 4];
        float4 b1 = *(const float4*)&vs[(t + 1) * 64 + tx * 4];
        const float a0v[4] = {a0.x, a0.y, a0.z, a0.w};
        const float b0v[4] = {b0.x, b0.y, b0.z, b0.w};
        const float a1v[4] = {a1.x, a1.y, a1.z, a1.w};
        const float b1v[4] = {b1.x, b1.y, b1.z, b1.w};
#pragma unroll
        for (int i = 0; i < 4; i++)
#pragma unroll
            for (int j = 0; j < 4; j++)
                acc[i][j] = fmaf(a0v[i], b0v[j], acc[i][j]);
#pragma unroll
        for (int i = 0; i < 4; i++)
#pragma unroll
            for (int j = 0; j < 4; j++)
                acc[i][j] = fmaf(a1v[i], b1v[j], acc[i][j]);
    }

    float* P = g_P + ((size_t)nh * NCHK + c) * (DH * DH);
#pragma unroll
    for (int i = 0; i < 4; i++)
#pragma unroll
        for (int j = 0; j < 4; j++)
            P[(ty * 4 + i) * 64 + tx * 4 + j] = acc[i][j];
}

// ---------------- exclusive prefix over chunks ----------------
__global__ __launch_bounds__(512)
void prefix_kv()
{
    const int nh = blockIdx.x >> 3;
    const int slab = blockIdx.x & 7;
    float* P = g_P + (size_t)nh * NCHK * (DH * DH);
    const int idx = slab * 512 + threadIdx.x;
    float run = 0.f;
#pragma unroll
    for (int c = 0; c < NCHK; c++) {
        float t = P[c * (DH * DH) + idx];
        P[c * (DH * DH) + idx] = run;
        run += t;
    }
}

// ---------------- attention output (112.5 KB smem -> 2 CTA/SM) ----------------
#define QSP 65
#define AO_QS    0
#define AO_AM    (128 * QSP)               // 8320 floats
#define AO_AUX   (AO_AM + 128 * 128)       // 24704 floats
#define AO_FLTS  (AO_AUX + 4096)           // 28800 floats
#define AO_BYTES (AO_FLTS * 4)             // 115200 bytes

__global__ __launch_bounds__(256, 2)
void attn_out(float* __restrict__ out)
{
    extern __shared__ float sm[];
    float* qs  = sm + AO_QS;    // 128 x 65
    float* Am  = sm + AO_AM;    // 128 x 128
    float* aux = sm + AO_AUX;   // 64 x 64 (kT half / Ss)

    const int c = blockIdx.x;
    const int nh = blockIdx.y;
    const int n = nh >> 4, h = nh & 15;
    const int t0 = c * CHK;
    const size_t base = ((size_t)(n * LSEQ + t0)) * DIM + h * DH;
    const int tid = threadIdx.x;
    const int lane = tid & 31;
    const int wid = tid >> 5;
    const int tx = tid & 15;
    const int ty = tid >> 4;

    for (int idx = tid; idx < CHK * DH; idx += 256) {
        int row = idx >> 6, col = idx & 63;
        qs[row * QSP + col] = g_Q[base + (size_t)row * DIM + col];
    }
    for (int idx = tid; idx < 64 * 64; idx += 256) {
        int s = idx >> 6, d = idx & 63;
        aux[d * 64 + s] = g_K[base + (size_t)s * DIM + d];
    }
    __syncthreads();

    // stage 1a: Am[:, 0:64] = causal(q @ kT0)
    {
        const int rr0 = wid * 16 + (lane >> 3) * 4;
        const int ss0 = (lane & 7) * 8;
        float acc[4][8];
#pragma unroll
        for (int i = 0; i < 4; i++)
#pragma unroll
            for (int j = 0; j < 8; j++) acc[i][j] = 0.f;
        for (int d = 0; d < DH; d++) {
            float a[4], b[8];
#pragma unroll
            for (int i = 0; i < 4; i++) a[i] = qs[(rr0 + i) * QSP + d];
#pragma unroll
            for (int j = 0; j < 8; j++) b[j] = aux[d * 64 + ss0 + j];
#pragma unroll
            for (int i = 0; i < 4; i++)
#pragma unroll
                for (int j = 0; j < 8; j++)
                    acc[i][j] = fmaf(a[i], b[j], acc[i][j]);
        }
#pragma unroll
        for (int i = 0; i < 4; i++) {
            int r = rr0 + i;
#pragma unroll
            for (int j = 0; j < 8; j++) {
                int s = ss0 + j;
                Am[r * CHK + s] = (s <= r) ? acc[i][j] : 0.f;
            }
        }
    }
    __syncthreads();

    for (int idx = tid; idx < 64 * 64; idx += 256) {
        int s = idx >> 6, d = idx & 63;
        aux[d * 64 + s] = g_K[base + (size_t)(64 + s) * DIM + d];
    }
    __syncthreads();

    // stage 1b: Am[64:128, 64:128] = causal(q @ kT1); zero Am[0:64, 64:128]
    {
        const int rr0 = 64 + wid * 8 + (lane >> 3) * 2;
        const int ss0 = 64 + (lane & 7) * 8;
        float acc[2][8];
#pragma unroll
        for (int i = 0; i < 2; i++)
#pragma unroll
            for (int j = 0; j < 8; j++) acc[i][j] = 0.f;
        for (int d = 0; d < DH; d++) {
            float a[2], b[8];
#pragma unroll
            for (int i = 0; i < 2; i++) a[i] = qs[(rr0 + i) * QSP + d];
#pragma unroll
            for (int j = 0; j < 8; j++) b[j] = aux[d * 64 + (ss0 - 64) + j];
#pragma unroll
            for (int i = 0; i < 2; i++)
#pragma unroll
                for (int j = 0; j < 8; j++)
                    acc[i][j] = fmaf(a[i], b[j], acc[i][j]);
        }
#pragma unroll
        for (int i = 0; i < 2; i++) {
            int r = rr0 + i;
#pragma unroll
            for (int j = 0; j < 8; j++) {
                int s = ss0 + j;
                Am[r * CHK + s] = (s <= r) ? acc[i][j] : 0.f;
            }
        }
        for (int idx = tid; idx < 64 * 64; idx += 256) {
            int r = idx >> 6, s2 = idx & 63;
            Am[r * CHK + 64 + s2] = 0.f;
        }
    }
    __syncthreads();

    {
        const float* Pp = g_P + ((size_t)nh * NCHK + c) * (DH * DH);
        for (int idx = tid; idx < DH * DH; idx += 256) aux[idx] = Pp[idx];
    }
    __syncthreads();

    float o[8][4];
#pragma unroll
    for (int i = 0; i < 8; i++)
#pragma unroll
        for (int j = 0; j < 4; j++) o[i][j] = 0.f;

    for (int d = 0; d < DH; d++) {
        float a[8], b[4];
#pragma unroll
        for (int i = 0; i < 8; i++) a[i] = qs[(ty * 8 + i) * QSP + d];
#pragma unroll
        for (int j = 0; j < 4; j++) b[j] = aux[d * 64 + tx * 4 + j];
#pragma unroll
        for (int i = 0; i < 8; i++)
#pragma unroll
            for (int j = 0; j < 4; j++)
                o[i][j] = fmaf(a[i], b[j], o[i][j]);
    }
    __syncthreads();

    float* vs = sm + AO_QS;
    for (int idx = tid; idx < CHK * DH; idx += 256) {
        int row = idx >> 6, col = idx & 63;
        vs[idx] = g_V[base + (size_t)row * DIM + col];
    }
    __syncthreads();

    const int sHi = (wid + 1) * 16;
    for (int s = 0; s < sHi; s++) {
        float a[8], b[4];
#pragma unroll
        for (int i = 0; i < 8; i++) a[i] = Am[(ty * 8 + i) * CHK + s];
#pragma unroll
        for (int j = 0; j < 4; j++) b[j] = vs[s * 64 + tx * 4 + j];
#pragma unroll
        for (int i = 0; i < 8; i++)
#pragma unroll
            for (int j = 0; j < 4; j++)
                o[i][j] = fmaf(a[i], b[j], o[i][j]);
    }

#pragma unroll
    for (int i = 0; i < 8; i++) {
        int r = ty * 8 + i;
#pragma unroll
        for (int j = 0; j < 4; j++)
            out[base + (size_t)r * DIM + tx * 4 + j] = o[i][j];
    }
}

// ---------------------------------------------------------------------------
extern "C" void kernel_launch(void* const* d_in, const int* in_sizes, int n_in,
                              void* d_out, int out_size)
{
    const float* query = (const float*)d_in[0];
    const float* key   = (const float*)d_in[1];
    const float* Wq    = (const float*)d_in[2];
    const float* Wk    = (const float*)d_in[3];
    const float* Wv    = (const float*)d_in[4];
    float* out = (float*)d_out;

    cudaFuncSetAttribute(proj_hmma, cudaFuncAttributeMaxDynamicSharedMemorySize, SMEM_TOTAL);
    cudaFuncSetAttribute(chunk_kv, cudaFuncAttributeMaxDynamicSharedMemorySize, 65536);
    cudaFuncSetAttribute(attn_out, cudaFuncAttributeMaxDynamicSharedMemorySize, AO_BYTES);

    // 1. fp16 conversion: X hi + scaled-lo, W and W/16
    conv_split<<<dim3(256, 5), 256>>>(query, key, Wq, Wk, Wv);

    // 2. projections on fp16 HMMA (2 passes) with fused per-head softmax
    proj_hmma<<<dim3(8, 32, 3), 256, SMEM_TOTAL>>>();

    // 3. chunked causal linear attention
    dim3 agrid(NCHK, NBATCH * NH);
    chunk_kv<<<agrid, 256, 65536>>>();
    prefix_kv<<<NBATCH * NH * 8, 512>>>();
    attn_out<<<agrid, 256, AO_BYTES>>>(out);
}

// round 12
// speedup vs baseline: 2.0965x; 1.3815x over previous
#include <cuda_runtime.h>
#include <cuda_fp16.h>
#include <cstdint>
#include <cstddef>

// ---------------- problem constants ----------------
#define NBATCH 2
#define LSEQ   2048
#define DIM    1024
#define NH     16
#define DH     64
#define CHK    128
#define NCHK   (LSEQ / CHK)      // 16
#define MROWS  (NBATCH * LSEQ)   // 4096

// ---------------- device scratch (no allocs allowed) ----------------
__device__ __align__(16) float g_Q[MROWS * DIM];
__device__ __align__(16) float g_K[MROWS * DIM];
__device__ __align__(16) float g_V[MROWS * DIM];
__device__ __align__(16) float g_P[NBATCH * NH * NCHK * DH * DH];
__device__ __align__(16) __half g_Xh[2][MROWS * DIM];    // 0=query 1=key (fp16)
__device__ __align__(16) __half g_Wh[3][DIM * DIM];      // Wq,Wk,Wv (fp16)

// ---------------- small helpers ----------------
__device__ __forceinline__ uint32_t smem_u32(const void* p) {
    uint32_t a;
    asm("{ .reg .u64 t; cvta.to.shared.u64 t, %1; cvt.u32.u64 %0, t; }" : "=r"(a) : "l"(p));
    return a;
}
__device__ __forceinline__ void cp16(uint32_t s, const void* g) {
    asm volatile("cp.async.cg.shared.global [%0], [%1], 16;" :: "r"(s), "l"(g));
}
#define CP_COMMIT() asm volatile("cp.async.commit_group;" ::: "memory")
#define CP_WAIT1()  asm volatile("cp.async.wait_group 1;" ::: "memory")

__device__ __forceinline__ void mma16816h(float* c, const uint32_t* a, const uint32_t* b) {
    asm volatile(
        "mma.sync.aligned.m16n8k16.row.col.f32.f16.f16.f32 "
        "{%0,%1,%2,%3}, {%4,%5,%6,%7}, {%8,%9}, {%0,%1,%2,%3};"
        : "+f"(c[0]), "+f"(c[1]), "+f"(c[2]), "+f"(c[3])
        : "r"(a[0]), "r"(a[1]), "r"(a[2]), "r"(a[3]), "r"(b[0]), "r"(b[1]));
}
__device__ __forceinline__ void ldsm4(uint32_t* r, uint32_t addr) {
    asm volatile("ldmatrix.sync.aligned.m8n8.x4.shared.b16 {%0,%1,%2,%3}, [%4];"
                 : "=r"(r[0]), "=r"(r[1]), "=r"(r[2]), "=r"(r[3]) : "r"(addr));
}

// ---------------- fp16 conversion (single precision level) ----------------
__global__ __launch_bounds__(256)
void conv_split(const float* __restrict__ q, const float* __restrict__ k,
                const float* __restrict__ wq, const float* __restrict__ wk,
                const float* __restrict__ wv)
{
    int y = blockIdx.y;
    const float* src;
    __half* dst;
    int n;
    switch (y) {
        case 0: src = q;  dst = g_Xh[0]; n = MROWS * DIM; break;
        case 1: src = k;  dst = g_Xh[1]; n = MROWS * DIM; break;
        case 2: src = wq; dst = g_Wh[0]; n = DIM * DIM;   break;
        case 3: src = wk; dst = g_Wh[1]; n = DIM * DIM;   break;
        default: src = wv; dst = g_Wh[2]; n = DIM * DIM;  break;
    }
    int n4 = n >> 2;
    for (int i = blockIdx.x * blockDim.x + threadIdx.x; i < n4;
         i += gridDim.x * blockDim.x) {
        float4 f = ((const float4*)src)[i];
        ushort4 u = make_ushort4(
            __half_as_ushort(__float2half(f.x)), __half_as_ushort(__float2half(f.y)),
            __half_as_ushort(__float2half(f.z)), __half_as_ushort(__float2half(f.w)));
        ((ushort4*)dst)[i] = u;
    }
}

// ---------------- HMMA projection GEMM (+ fused per-head softmax) ----------------
// Out[m,n] = sum_k X[m,k]*W[n,k], single fp16 pass, fp32 accum.
// 128x128 CTA tile, BK=64 halves (16 iters), 8 warps of 64x32, ldmatrix.x4,
// XOR-swizzled 128B rows, 3-stage cp.async ring.
#define STAGE_BYTES 32768
#define SMEM_TOTAL  (3 * STAGE_BYTES)     // 96 KB

__device__ __forceinline__ uint32_t swz(int row, int c) {
    return (uint32_t)(row * 128 + ((c ^ (row & 7)) << 4));
}

__global__ __launch_bounds__(256, 2)
void proj_hmma()
{
    extern __shared__ char smem[];
    const uint32_t sb = smem_u32(smem);

    const int tid = threadIdx.x;
    const int wid = tid >> 5;
    const int lane = tid & 31;
    const int wm = wid >> 2;       // 0..1
    const int wn = wid & 3;        // 0..3
    const int z = blockIdx.z;

    const __half* __restrict__ A = g_Xh[z ? 1 : 0];
    const __half* __restrict__ B = g_Wh[z];
    float* __restrict__ Out = (z == 0) ? g_Q : (z == 1) ? g_K : g_V;

    const int m0 = blockIdx.y * 128;
    const int n0 = blockIdx.x * 128;

    float acc[4][4][4];
#pragma unroll
    for (int i = 0; i < 4; i++)
#pragma unroll
        for (int j = 0; j < 4; j++)
#pragma unroll
            for (int r = 0; r < 4; r++) acc[i][j][r] = 0.f;

    const int lrow = tid >> 1;
    const int lc4  = (tid & 1) * 4;
    auto load_tile = [&](int kk, int stg) {
        const int k0 = kk * 64;
        const uint32_t sa = sb + stg * STAGE_BYTES;
        const uint32_t sbB = sa + 16384;
        const __half* ga = A + (size_t)(m0 + lrow) * DIM + k0 + lc4 * 8;
        const __half* gb = B + (size_t)(n0 + lrow) * DIM + k0 + lc4 * 8;
#pragma unroll
        for (int c = 0; c < 4; c++) {
            cp16(sa  + swz(lrow, lc4 + c), ga + c * 8);
            cp16(sbB + swz(lrow, lc4 + c), gb + c * 8);
        }
    };

    const int a_row = (lane & 7) + ((lane >> 3) & 1) * 8;
    const int a_cofs = lane >> 4;
    const int b_row0 = ((lane >> 4) & 1) * 8 + (lane & 7);
    const int b_cofs = (lane >> 3) & 1;

    load_tile(0, 0); CP_COMMIT();
    load_tile(1, 1); CP_COMMIT();

    for (int kk = 0; kk < 16; kk++) {
        const int stg = kk % 3;
        CP_WAIT1();
        __syncthreads();
        if (kk + 2 < 16) { load_tile(kk + 2, (kk + 2) % 3); CP_COMMIT(); }

        const uint32_t sa = sb + stg * STAGE_BYTES;
        const uint32_t sbB = sa + 16384;

#pragma unroll
        for (int ks = 0; ks < 4; ks++) {
            const int c0 = ks * 2;
            uint32_t a[4][4], b[8];
#pragma unroll
            for (int i = 0; i < 4; i++) {
                const int r0 = wm * 64 + i * 16;
                ldsm4(a[i], sa + swz(r0 + a_row, c0 + a_cofs));
            }
#pragma unroll
            for (int jp = 0; jp < 2; jp++) {
                const int c0b = wn * 32 + jp * 16;
                ldsm4(&b[jp * 4], sbB + swz(c0b + b_row0, c0 + b_cofs));
            }
#pragma unroll
            for (int i = 0; i < 4; i++)
#pragma unroll
                for (int j = 0; j < 4; j++)
                    mma16816h(acc[i][j], a[i], &b[j * 2]);
        }
    }

    // ---------------- epilogue ----------------
    const int g = lane >> 2;
    const int tg = lane & 3;
    __syncthreads();

    if (z < 2) {
        float* red = (float*)smem;   // [128 rows][2 seg][2 pair]
        const int seg = wn >> 1;
        const int pr = wn & 1;

        float ml[4][2];
#pragma unroll
        for (int i = 0; i < 4; i++)
#pragma unroll
            for (int h = 0; h < 2; h++) {
                float m = acc[i][0][h * 2];
#pragma unroll
                for (int j = 0; j < 4; j++) {
                    m = fmaxf(m, acc[i][j][h * 2]);
                    m = fmaxf(m, acc[i][j][h * 2 + 1]);
                }
                m = fmaxf(m, __shfl_xor_sync(0xffffffffu, m, 1));
                m = fmaxf(m, __shfl_xor_sync(0xffffffffu, m, 2));
                ml[i][h] = m;
            }
        if (tg == 0) {
#pragma unroll
            for (int i = 0; i < 4; i++)
#pragma unroll
                for (int h = 0; h < 2; h++) {
                    int row = wm * 64 + i * 16 + h * 8 + g;
                    red[(row * 2 + seg) * 2 + pr] = ml[i][h];
                }
        }
        __syncthreads();
        float mseg[4][2];
#pragma unroll
        for (int i = 0; i < 4; i++)
#pragma unroll
            for (int h = 0; h < 2; h++) {
                int row = wm * 64 + i * 16 + h * 8 + g;
                mseg[i][h] = fmaxf(red[(row * 2 + seg) * 2 + 0],
                                   red[(row * 2 + seg) * 2 + 1]);
            }
        __syncthreads();

        float sl[4][2];
#pragma unroll
        for (int i = 0; i < 4; i++)
#pragma unroll
            for (int h = 0; h < 2; h++) {
                float s = 0.f;
#pragma unroll
                for (int j = 0; j < 4; j++) {
                    float e0 = __expf(acc[i][j][h * 2]     - mseg[i][h]);
                    float e1 = __expf(acc[i][j][h * 2 + 1] - mseg[i][h]);
                    acc[i][j][h * 2] = e0; acc[i][j][h * 2 + 1] = e1;
                    s += e0 + e1;
                }
                s += __shfl_xor_sync(0xffffffffu, s, 1);
                s += __shfl_xor_sync(0xffffffffu, s, 2);
                sl[i][h] = s;
            }
        if (tg == 0) {
#pragma unroll
            for (int i = 0; i < 4; i++)
#pragma unroll
                for (int h = 0; h < 2; h++) {
                    int row = wm * 64 + i * 16 + h * 8 + g;
                    red[(row * 2 + seg) * 2 + pr] = sl[i][h];
                }
        }
        __syncthreads();
#pragma unroll
        for (int i = 0; i < 4; i++)
#pragma unroll
            for (int h = 0; h < 2; h++) {
                int row = wm * 64 + i * 16 + h * 8 + g;
                float inv = 1.0f / (red[(row * 2 + seg) * 2 + 0] +
                                    red[(row * 2 + seg) * 2 + 1]);
#pragma unroll
                for (int j = 0; j < 4; j++) {
                    acc[i][j][h * 2]     *= inv;
                    acc[i][j][h * 2 + 1] *= inv;
                }
            }
    }

#pragma unroll
    for (int i = 0; i < 4; i++) {
        const int r0 = m0 + wm * 64 + i * 16 + g;
#pragma unroll
        for (int j = 0; j < 4; j++) {
            const int cc = n0 + wn * 32 + j * 8 + tg * 2;
            *(float2*)&Out[(size_t)r0 * DIM + cc] = make_float2(acc[i][j][0], acc[i][j][1]);
            *(float2*)&Out[(size_t)(r0 + 8) * DIM + cc] = make_float2(acc[i][j][2], acc[i][j][3]);
        }
    }
}

// ---------------- per-chunk KV outer-product sums ----------------
__global__ __launch_bounds__(256)
void chunk_kv()
{
    extern __shared__ float sm[];
    float* ks = sm;          // 128*64
    float* vs = sm + 8192;   // 128*64

    const int c = blockIdx.x;
    const int nh = blockIdx.y;
    const int n = nh >> 4, h = nh & 15;
    const int t0 = c * CHK;
    const size_t base = ((size_t)(n * LSEQ + t0)) * DIM + h * DH;

    for (int idx = threadIdx.x; idx < CHK * DH; idx += 256) {
        int row = idx >> 6, col = idx & 63;
        ks[idx] = g_K[base + (size_t)row * DIM + col];
        vs[idx] = g_V[base + (size_t)row * DIM + col];
    }
    __syncthreads();

    const int tx = threadIdx.x & 15;
    const int ty = threadIdx.x >> 4;
    float acc[4][4];
#pragma unroll
    for (int i = 0; i < 4; i++)
#pragma unroll
        for (int j = 0; j < 4; j++) acc[i][j] = 0.f;

    for (int t = 0; t < CHK; t += 2) {
        float4 a0 = *(const float4*)&ks[t * 64 + ty * 4];
        float4 b0 = *(const float4*)&vs[t * 64 + tx * 4];
        float4 a1 = *(const float4*)&ks[(t + 1) * 64 + ty * 4];
        float4 b1 = *(const float4*)&vs[(t + 1) * 64 + tx * 4];
        const float a0v[4] = {a0.x, a0.y, a0.z, a0.w};
        const float b0v[4] = {b0.x, b0.y, b0.z, b0.w};
        const float a1v[4] = {a1.x, a1.y, a1.z, a1.w};
        const float b1v[4] = {b1.x, b1.y, b1.z, b1.w};
#pragma unroll
        for (int i = 0; i < 4; i++)
#pragma unroll
            for (int j = 0; j < 4; j++)
                acc[i][j] = fmaf(a0v[i], b0v[j], acc[i][j]);
#pragma unroll
        for (int i = 0; i < 4; i++)
#pragma unroll
            for (int j = 0; j < 4; j++)
                acc[i][j] = fmaf(a1v[i], b1v[j], acc[i][j]);
    }

    float* P = g_P + ((size_t)nh * NCHK + c) * (DH * DH);
#pragma unroll
    for (int i = 0; i < 4; i++)
#pragma unroll
        for (int j = 0; j < 4; j++)
            P[(ty * 4 + i) * 64 + tx * 4 + j] = acc[i][j];
}

// ---------------- exclusive prefix over chunks ----------------
__global__ __launch_bounds__(512)
void prefix_kv()
{
    const int nh = blockIdx.x >> 3;
    const int slab = blockIdx.x & 7;
    float* P = g_P + (size_t)nh * NCHK * (DH * DH);
    const int idx = slab * 512 + threadIdx.x;
    float run = 0.f;
#pragma unroll
    for (int c = 0; c < NCHK; c++) {
        float t = P[c * (DH * DH) + idx];
        P[c * (DH * DH) + idx] = run;
        run += t;
    }
}

// ---------------- attention output (112.5 KB smem -> 2 CTA/SM) ----------------
#define QSP 65
#define AO_QS    0
#define AO_AM    (128 * QSP)               // 8320 floats
#define AO_AUX   (AO_AM + 128 * 128)       // 24704 floats
#define AO_FLTS  (AO_AUX + 4096)           // 28800 floats
#define AO_BYTES (AO_FLTS * 4)             // 115200 bytes

__global__ __launch_bounds__(256, 2)
void attn_out(float* __restrict__ out)
{
    extern __shared__ float sm[];
    float* qs  = sm + AO_QS;    // 128 x 65
    float* Am  = sm + AO_AM;    // 128 x 128
    float* aux = sm + AO_AUX;   // 64 x 64 (kT half / Ss)

    const int c = blockIdx.x;
    const int nh = blockIdx.y;
    const int n = nh >> 4, h = nh & 15;
    const int t0 = c * CHK;
    const size_t base = ((size_t)(n * LSEQ + t0)) * DIM + h * DH;
    const int tid = threadIdx.x;
    const int lane = tid & 31;
    const int wid = tid >> 5;
    const int tx = tid & 15;
    const int ty = tid >> 4;

    for (int idx = tid; idx < CHK * DH; idx += 256) {
        int row = idx >> 6, col = idx & 63;
        qs[row * QSP + col] = g_Q[base + (size_t)row * DIM + col];
    }
    for (int idx = tid; idx < 64 * 64; idx += 256) {
        int s = idx >> 6, d = idx & 63;
        aux[d * 64 + s] = g_K[base + (size_t)s * DIM + d];
    }
    __syncthreads();

    // stage 1a: Am[:, 0:64] = causal(q @ kT0)
    {
        const int rr0 = wid * 16 + (lane >> 3) * 4;
        const int ss0 = (lane & 7) * 8;
        float acc[4][8];
#pragma unroll
        for (int i = 0; i < 4; i++)
#pragma unroll
            for (int j = 0; j < 8; j++) acc[i][j] = 0.f;
        for (int d = 0; d < DH; d++) {
            float a[4], b[8];
#pragma unroll
            for (int i = 0; i < 4; i++) a[i] = qs[(rr0 + i) * QSP + d];
#pragma unroll
            for (int j = 0; j < 8; j++) b[j] = aux[d * 64 + ss0 + j];
#pragma unroll
            for (int i = 0; i < 4; i++)
#pragma unroll
                for (int j = 0; j < 8; j++)
                    acc[i][j] = fmaf(a[i], b[j], acc[i][j]);
        }
#pragma unroll
        for (int i = 0; i < 4; i++) {
            int r = rr0 + i;
#pragma unroll
            for (int j = 0; j < 8; j++) {
                int s = ss0 + j;
                Am[r * CHK + s] = (s <= r) ? acc[i][j] : 0.f;
            }
        }
    }
    __syncthreads();

    for (int idx = tid; idx < 64 * 64; idx += 256) {
        int s = idx >> 6, d = idx & 63;
        aux[d * 64 + s] = g_K[base + (size_t)(64 + s) * DIM + d];
    }
    __syncthreads();

    // stage 1b: Am[64:128, 64:128] = causal(q @ kT1); zero Am[0:64, 64:128]
    {
        const int rr0 = 64 + wid * 8 + (lane >> 3) * 2;
        const int ss0 = 64 + (lane & 7) * 8;
        float acc[2][8];
#pragma unroll
        for (int i = 0; i < 2; i++)
#pragma unroll
            for (int j = 0; j < 8; j++) acc[i][j] = 0.f;
        for (int d = 0; d < DH; d++) {
            float a[2], b[8];
#pragma unroll
            for (int i = 0; i < 2; i++) a[i] = qs[(rr0 + i) * QSP + d];
#pragma unroll
            for (int j = 0; j < 8; j++) b[j] = aux[d * 64 + (ss0 - 64) + j];
#pragma unroll
            for (int i = 0; i < 2; i++)
#pragma unroll
                for (int j = 0; j < 8; j++)
                    acc[i][j] = fmaf(a[i], b[j], acc[i][j]);
        }
#pragma unroll
        for (int i = 0; i < 2; i++) {
            int r = rr0 + i;
#pragma unroll
            for (int j = 0; j < 8; j++) {
                int s = ss0 + j;
                Am[r * CHK + s] = (s <= r) ? acc[i][j] : 0.f;
            }
        }
        for (int idx = tid; idx < 64 * 64; idx += 256) {
            int r = idx >> 6, s2 = idx & 63;
            Am[r * CHK + 64 + s2] = 0.f;
        }
    }
    __syncthreads();

    {
        const float* Pp = g_P + ((size_t)nh * NCHK + c) * (DH * DH);
        for (int idx = tid; idx < DH * DH; idx += 256) aux[idx] = Pp[idx];
    }
    __syncthreads();

    float o[8][4];
#pragma unroll
    for (int i = 0; i < 8; i++)
#pragma unroll
        for (int j = 0; j < 4; j++) o[i][j] = 0.f;

    for (int d = 0; d < DH; d++) {
        float a[8], b[4];
#pragma unroll
        for (int i = 0; i < 8; i++) a[i] = qs[(ty * 8 + i) * QSP + d];
#pragma unroll
        for (int j = 0; j < 4; j++) b[j] = aux[d * 64 + tx * 4 + j];
#pragma unroll
        for (int i = 0; i < 8; i++)
#pragma unroll
            for (int j = 0; j < 4; j++)
                o[i][j] = fmaf(a[i], b[j], o[i][j]);
    }
    __syncthreads();

    float* vs = sm + AO_QS;
    for (int idx = tid; idx < CHK * DH; idx += 256) {
        int row = idx >> 6, col = idx & 63;
        vs[idx] = g_V[base + (size_t)row * DIM + col];
    }
    __syncthreads();

    const int sHi = (wid + 1) * 16;
    for (int s = 0; s < sHi; s++) {
        float a[8], b[4];
#pragma unroll
        for (int i = 0; i < 8; i++) a[i] = Am[(ty * 8 + i) * CHK + s];
#pragma unroll
        for (int j = 0; j < 4; j++) b[j] = vs[s * 64 + tx * 4 + j];
#pragma unroll
        for (int i = 0; i < 8; i++)
#pragma unroll
            for (int j = 0; j < 4; j++)
                o[i][j] = fmaf(a[i], b[j], o[i][j]);
    }

#pragma unroll
    for (int i = 0; i < 8; i++) {
        int r = ty * 8 + i;
#pragma unroll
        for (int j = 0; j < 4; j++)
            out[base + (size_t)r * DIM + tx * 4 + j] = o[i][j];
    }
}

// ---------------------------------------------------------------------------
extern "C" void kernel_launch(void* const* d_in, const int* in_sizes, int n_in,
                              void* d_out, int out_size)
{
    const float* query = (const float*)d_in[0];
    const float* key   = (const float*)d_in[1];
    const float* Wq    = (const float*)d_in[2];
    const float* Wk    = (const float*)d_in[3];
    const float* Wv    = (const float*)d_in[4];
    float* out = (float*)d_out;

    cudaFuncSetAttribute(proj_hmma, cudaFuncAttributeMaxDynamicSharedMemorySize, SMEM_TOTAL);
    cudaFuncSetAttribute(chunk_kv, cudaFuncAttributeMaxDynamicSharedMemorySize, 65536);
    cudaFuncSetAttribute(attn_out, cudaFuncAttributeMaxDynamicSharedMemorySize, AO_BYTES);

    // 1. fp16 conversion (X and W, single precision level)
    conv_split<<<dim3(256, 5), 256>>>(query, key, Wq, Wk, Wv);

    // 2. projections on fp16 HMMA (single pass) with fused per-head softmax
    proj_hmma<<<dim3(8, 32, 3), 256, SMEM_TOTAL>>>();

    // 3. chunked causal linear attention
    dim3 agrid(NCHK, NBATCH * NH);
    chunk_kv<<<agrid, 256, 65536>>>();
    prefix_kv<<<NBATCH * NH * 8, 512>>>();
    attn_out<<<agrid, 256, AO_BYTES>>>(out);
}

// round 13
// speedup vs baseline: 3.5868x; 1.7108x over previous
#include <cuda_runtime.h>
#include <cuda_fp16.h>
#include <cstdint>
#include <cstddef>

// ---------------- problem constants ----------------
#define NBATCH 2
#define LSEQ   2048
#define DIM    1024
#define NH     16
#define DH     64
#define CHK    128
#define NCHK   (LSEQ / CHK)      // 16
#define MROWS  (NBATCH * LSEQ)   // 4096

// ---------------- device scratch (no allocs allowed) ----------------
__device__ __align__(16) __half g_Xh[2][MROWS * DIM];    // fp16 inputs (q,k)
__device__ __align__(16) __half g_Wh[3][DIM * DIM];      // fp16 weights
__device__ __align__(16) __half g_Oh[3][MROWS * DIM];    // fp16 projected Q,K,V
__device__ __align__(16) float  g_P[NBATCH * NH * NCHK * DH * DH];   // chunk sums
__device__ __align__(16) __half g_Sh[NBATCH * NH * NCHK * DH * DH];  // excl prefix fp16

// ---------------- small helpers ----------------
__device__ __forceinline__ uint32_t smem_u32(const void* p) {
    uint32_t a;
    asm("{ .reg .u64 t; cvta.to.shared.u64 t, %1; cvt.u32.u64 %0, t; }" : "=r"(a) : "l"(p));
    return a;
}
__device__ __forceinline__ void cp16(uint32_t s, const void* g) {
    asm volatile("cp.async.cg.shared.global [%0], [%1], 16;" :: "r"(s), "l"(g));
}
#define CP_COMMIT() asm volatile("cp.async.commit_group;" ::: "memory")
#define CP_WAIT1()  asm volatile("cp.async.wait_group 1;" ::: "memory")
#define CP_WAIT0()  asm volatile("cp.async.wait_group 0;" ::: "memory")

__device__ __forceinline__ void mma16816h(float* c, const uint32_t* a, const uint32_t* b) {
    asm volatile(
        "mma.sync.aligned.m16n8k16.row.col.f32.f16.f16.f32 "
        "{%0,%1,%2,%3}, {%4,%5,%6,%7}, {%8,%9}, {%0,%1,%2,%3};"
        : "+f"(c[0]), "+f"(c[1]), "+f"(c[2]), "+f"(c[3])
        : "r"(a[0]), "r"(a[1]), "r"(a[2]), "r"(a[3]), "r"(b[0]), "r"(b[1]));
}
__device__ __forceinline__ void ldsm4(uint32_t* r, uint32_t addr) {
    asm volatile("ldmatrix.sync.aligned.m8n8.x4.shared.b16 {%0,%1,%2,%3}, [%4];"
                 : "=r"(r[0]), "=r"(r[1]), "=r"(r[2]), "=r"(r[3]) : "r"(addr));
}
__device__ __forceinline__ void ldsm4t(uint32_t* r, uint32_t addr) {
    asm volatile("ldmatrix.sync.aligned.m8n8.x4.trans.shared.b16 {%0,%1,%2,%3}, [%4];"
                 : "=r"(r[0]), "=r"(r[1]), "=r"(r[2]), "=r"(r[3]) : "r"(addr));
}

// swizzled byte offset: 128B-pitch rows, 16B chunk c (0..7)
__device__ __forceinline__ uint32_t swz(int row, int c) {
    return (uint32_t)(row * 128 + ((c ^ (row & 7)) << 4));
}
// 256B-pitch rows, 16 chunks: XOR low 3 bits only
__device__ __forceinline__ uint32_t swzA(int row, int c) {
    return (uint32_t)(row * 256 + (((c & 8) | ((c & 7) ^ (row & 7))) << 4));
}

// ---------------- fp16 conversion ----------------
__global__ __launch_bounds__(256)
void conv_split(const float* __restrict__ q, const float* __restrict__ k,
                const float* __restrict__ wq, const float* __restrict__ wk,
                const float* __restrict__ wv)
{
    int y = blockIdx.y;
    const float* src;
    __half* dst;
    int n;
    switch (y) {
        case 0: src = q;  dst = g_Xh[0]; n = MROWS * DIM; break;
        case 1: src = k;  dst = g_Xh[1]; n = MROWS * DIM; break;
        case 2: src = wq; dst = g_Wh[0]; n = DIM * DIM;   break;
        case 3: src = wk; dst = g_Wh[1]; n = DIM * DIM;   break;
        default: src = wv; dst = g_Wh[2]; n = DIM * DIM;  break;
    }
    int n4 = n >> 2;
    for (int i = blockIdx.x * blockDim.x + threadIdx.x; i < n4;
         i += gridDim.x * blockDim.x) {
        float4 f = ((const float4*)src)[i];
        ushort4 u = make_ushort4(
            __half_as_ushort(__float2half(f.x)), __half_as_ushort(__float2half(f.y)),
            __half_as_ushort(__float2half(f.z)), __half_as_ushort(__float2half(f.w)));
        ((ushort4*)dst)[i] = u;
    }
}

// ---------------- HMMA projection GEMM (+ fused softmax, fp16 out) ----------------
#define STAGE_BYTES 32768
#define SMEM_TOTAL  (3 * STAGE_BYTES)

__global__ __launch_bounds__(256, 2)
void proj_hmma()
{
    extern __shared__ char smem[];
    const uint32_t sb = smem_u32(smem);

    const int tid = threadIdx.x;
    const int wid = tid >> 5;
    const int lane = tid & 31;
    const int wm = wid >> 2;
    const int wn = wid & 3;
    const int z = blockIdx.z;

    const __half* __restrict__ A = g_Xh[z ? 1 : 0];
    const __half* __restrict__ B = g_Wh[z];
    __half* __restrict__ Out = g_Oh[z];

    const int m0 = blockIdx.y * 128;
    const int n0 = blockIdx.x * 128;

    float acc[4][4][4];
#pragma unroll
    for (int i = 0; i < 4; i++)
#pragma unroll
        for (int j = 0; j < 4; j++)
#pragma unroll
            for (int r = 0; r < 4; r++) acc[i][j][r] = 0.f;

    const int lrow = tid >> 1;
    const int lc4  = (tid & 1) * 4;
    auto load_tile = [&](int kk, int stg) {
        const int k0 = kk * 64;
        const uint32_t sa = sb + stg * STAGE_BYTES;
        const uint32_t sbB = sa + 16384;
        const __half* ga = A + (size_t)(m0 + lrow) * DIM + k0 + lc4 * 8;
        const __half* gb = B + (size_t)(n0 + lrow) * DIM + k0 + lc4 * 8;
#pragma unroll
        for (int c = 0; c < 4; c++) {
            cp16(sa  + swz(lrow, lc4 + c), ga + c * 8);
            cp16(sbB + swz(lrow, lc4 + c), gb + c * 8);
        }
    };

    const int a_row = (lane & 7) + ((lane >> 3) & 1) * 8;
    const int a_cofs = lane >> 4;
    const int b_row0 = ((lane >> 4) & 1) * 8 + (lane & 7);
    const int b_cofs = (lane >> 3) & 1;

    load_tile(0, 0); CP_COMMIT();
    load_tile(1, 1); CP_COMMIT();

    for (int kk = 0; kk < 16; kk++) {
        const int stg = kk % 3;
        CP_WAIT1();
        __syncthreads();
        if (kk + 2 < 16) { load_tile(kk + 2, (kk + 2) % 3); CP_COMMIT(); }

        const uint32_t sa = sb + stg * STAGE_BYTES;
        const uint32_t sbB = sa + 16384;

#pragma unroll
        for (int ks = 0; ks < 4; ks++) {
            const int c0 = ks * 2;
            uint32_t a[4][4], b[8];
#pragma unroll
            for (int i = 0; i < 4; i++)
                ldsm4(a[i], sa + swz(wm * 64 + i * 16 + a_row, c0 + a_cofs));
#pragma unroll
            for (int jp = 0; jp < 2; jp++)
                ldsm4(&b[jp * 4], sbB + swz(wn * 32 + jp * 16 + b_row0, c0 + b_cofs));
#pragma unroll
            for (int i = 0; i < 4; i++)
#pragma unroll
                for (int j = 0; j < 4; j++)
                    mma16816h(acc[i][j], a[i], &b[j * 2]);
        }
    }

    const int g = lane >> 2;
    const int tg = lane & 3;
    __syncthreads();

    if (z < 2) {
        float* red = (float*)smem;
        const int seg = wn >> 1;
        const int pr = wn & 1;

        float ml[4][2];
#pragma unroll
        for (int i = 0; i < 4; i++)
#pragma unroll
            for (int h = 0; h < 2; h++) {
                float m = acc[i][0][h * 2];
#pragma unroll
                for (int j = 0; j < 4; j++) {
                    m = fmaxf(m, acc[i][j][h * 2]);
                    m = fmaxf(m, acc[i][j][h * 2 + 1]);
                }
                m = fmaxf(m, __shfl_xor_sync(0xffffffffu, m, 1));
                m = fmaxf(m, __shfl_xor_sync(0xffffffffu, m, 2));
                ml[i][h] = m;
            }
        if (tg == 0) {
#pragma unroll
            for (int i = 0; i < 4; i++)
#pragma unroll
                for (int h = 0; h < 2; h++) {
                    int row = wm * 64 + i * 16 + h * 8 + g;
                    red[(row * 2 + seg) * 2 + pr] = ml[i][h];
                }
        }
        __syncthreads();
        float mseg[4][2];
#pragma unroll
        for (int i = 0; i < 4; i++)
#pragma unroll
            for (int h = 0; h < 2; h++) {
                int row = wm * 64 + i * 16 + h * 8 + g;
                mseg[i][h] = fmaxf(red[(row * 2 + seg) * 2 + 0],
                                   red[(row * 2 + seg) * 2 + 1]);
            }
        __syncthreads();

        float sl[4][2];
#pragma unroll
        for (int i = 0; i < 4; i++)
#pragma unroll
            for (int h = 0; h < 2; h++) {
                float s = 0.f;
#pragma unroll
                for (int j = 0; j < 4; j++) {
                    float e0 = __expf(acc[i][j][h * 2]     - mseg[i][h]);
                    float e1 = __expf(acc[i][j][h * 2 + 1] - mseg[i][h]);
                    acc[i][j][h * 2] = e0; acc[i][j][h * 2 + 1] = e1;
                    s += e0 + e1;
                }
                s += __shfl_xor_sync(0xffffffffu, s, 1);
                s += __shfl_xor_sync(0xffffffffu, s, 2);
                sl[i][h] = s;
            }
        if (tg == 0) {
#pragma unroll
            for (int i = 0; i < 4; i++)
#pragma unroll
                for (int h = 0; h < 2; h++) {
                    int row = wm * 64 + i * 16 + h * 8 + g;
                    red[(row * 2 + seg) * 2 + pr] = sl[i][h];
                }
        }
        __syncthreads();
#pragma unroll
        for (int i = 0; i < 4; i++)
#pragma unroll
            for (int h = 0; h < 2; h++) {
                int row = wm * 64 + i * 16 + h * 8 + g;
                float inv = 1.0f / (red[(row * 2 + seg) * 2 + 0] +
                                    red[(row * 2 + seg) * 2 + 1]);
#pragma unroll
                for (int j = 0; j < 4; j++) {
                    acc[i][j][h * 2]     *= inv;
                    acc[i][j][h * 2 + 1] *= inv;
                }
            }
    }

    // store fp16
#pragma unroll
    for (int i = 0; i < 4; i++) {
        const int r0 = m0 + wm * 64 + i * 16 + g;
#pragma unroll
        for (int j = 0; j < 4; j++) {
            const int cc = n0 + wn * 32 + j * 8 + tg * 2;
            *(__half2*)&Out[(size_t)r0 * DIM + cc] =
                __floats2half2_rn(acc[i][j][0], acc[i][j][1]);
            *(__half2*)&Out[(size_t)(r0 + 8) * DIM + cc] =
                __floats2half2_rn(acc[i][j][2], acc[i][j][3]);
        }
    }
}

// ---------------- per-chunk KV sums on HMMA: P = k^T v (64x64x128) ----------------
__global__ __launch_bounds__(256)
void chunk_kv()
{
    extern __shared__ char smem[];
    const uint32_t sb = smem_u32(smem);   // KH @0 (16KB), VH @16384 (16KB)

    const int c = blockIdx.x;
    const int nh = blockIdx.y;
    const int n = nh >> 4, h = nh & 15;
    const size_t base = ((size_t)(n * LSEQ + c * CHK)) * DIM + h * DH;
    const int tid = threadIdx.x;
    const int lane = tid & 31;
    const int wid = tid >> 5;

    {
        int lrow = tid >> 1, lc4 = (tid & 1) * 4;
        const __half* gk = g_Oh[1] + base + (size_t)lrow * DIM;
        const __half* gv = g_Oh[2] + base + (size_t)lrow * DIM;
#pragma unroll
        for (int c4 = 0; c4 < 4; c4++) {
            cp16(sb + swz(lrow, lc4 + c4), gk + (lc4 + c4) * 8);
            cp16(sb + 16384 + swz(lrow, lc4 + c4), gv + (lc4 + c4) * 8);
        }
    }
    CP_COMMIT(); CP_WAIT0(); __syncthreads();

    const int wmc = wid >> 1;    // d1 block (m16)
    const int wnc = wid & 1;     // d2 block (n32)
    const int ta_krow = ((lane >> 4) << 3) + (lane & 7);
    const int ta_mch  = (lane >> 3) & 1;
    const int tb_krow = (((lane >> 3) & 1) << 3) + (lane & 7);
    const int tb_nch  = lane >> 4;

    float acc[4][4];
#pragma unroll
    for (int j = 0; j < 4; j++)
#pragma unroll
        for (int r = 0; r < 4; r++) acc[j][r] = 0.f;

#pragma unroll
    for (int kt = 0; kt < 8; kt++) {
        const int t0 = kt * 16;
        uint32_t a[4], b[8];
        ldsm4t(a, sb + swz(t0 + ta_krow, 2 * wmc + ta_mch));
#pragma unroll
        for (int jp = 0; jp < 2; jp++)
            ldsm4t(&b[jp * 4], sb + 16384 + swz(t0 + tb_krow, 4 * wnc + 2 * jp + tb_nch));
#pragma unroll
        for (int j = 0; j < 4; j++)
            mma16816h(acc[j], a, &b[j * 2]);
    }

    const int g = lane >> 2, tg = lane & 3;
    float* P = g_P + ((size_t)nh * NCHK + c) * (DH * DH);
#pragma unroll
    for (int j = 0; j < 4; j++) {
        int row = 16 * wmc + g;
        int col = 32 * wnc + 8 * j + 2 * tg;
        *(float2*)&P[row * 64 + col] = make_float2(acc[j][0], acc[j][1]);
        *(float2*)&P[(row + 8) * 64 + col] = make_float2(acc[j][2], acc[j][3]);
    }
}

// ---------------- exclusive prefix -> fp16 ----------------
__global__ __launch_bounds__(512)
void prefix_kv()
{
    const int nh = blockIdx.x >> 3;
    const int slab = blockIdx.x & 7;
    const float* P = g_P + (size_t)nh * NCHK * (DH * DH);
    __half* S = g_Sh + (size_t)nh * NCHK * (DH * DH);
    const int idx = slab * 512 + threadIdx.x;
    float run = 0.f;
#pragma unroll
    for (int c = 0; c < NCHK; c++) {
        S[c * (DH * DH) + idx] = __float2half(run);
        run += P[c * (DH * DH) + idx];
    }
}

// ---------------- attention output on HMMA ----------------
// smem: QH 16K @0, KH 16K @16384, VH 16K @32768, SH 8K @49152, AH 32K @57344
#define AT_QH 0
#define AT_KH 16384
#define AT_VH 32768
#define AT_SH 49152
#define AT_AH 57344
#define AT_BYTES (AT_AH + 32768)   // 90112

__global__ __launch_bounds__(256, 2)
void attn_out(float* __restrict__ out)
{
    extern __shared__ char smem[];
    const uint32_t sb = smem_u32(smem);

    const int c = blockIdx.x;
    const int nh = blockIdx.y;
    const int n = nh >> 4, h = nh & 15;
    const size_t base = ((size_t)(n * LSEQ + c * CHK)) * DIM + h * DH;
    const int tid = threadIdx.x;
    const int lane = tid & 31;
    const int wid = tid >> 5;
    const int g = lane >> 2, tg = lane & 3;

    const int a_row = (lane & 7) + ((lane >> 3) & 1) * 8;
    const int a_cofs = lane >> 4;
    const int b_row0 = ((lane >> 4) & 1) * 8 + (lane & 7);
    const int b_cofs = (lane >> 3) & 1;
    const int tb_krow = (((lane >> 3) & 1) << 3) + (lane & 7);
    const int tb_nch  = lane >> 4;

    // ---- load QH/KH/VH (128 rows) + SH (64 rows) ----
    {
        int lrow = tid >> 1, lc4 = (tid & 1) * 4;
        const __half* gq = g_Oh[0] + base + (size_t)lrow * DIM;
        const __half* gk = g_Oh[1] + base + (size_t)lrow * DIM;
        const __half* gv = g_Oh[2] + base + (size_t)lrow * DIM;
#pragma unroll
        for (int c4 = 0; c4 < 4; c4++) {
            int ch = lc4 + c4;
            cp16(sb + AT_QH + swz(lrow, ch), gq + ch * 8);
            cp16(sb + AT_KH + swz(lrow, ch), gk + ch * 8);
            cp16(sb + AT_VH + swz(lrow, ch), gv + ch * 8);
        }
        if (tid < 128) {
            const __half* gs = g_Sh + ((size_t)nh * NCHK + c) * (DH * DH) + lrow * 64;
#pragma unroll
            for (int c4 = 0; c4 < 4; c4++) {
                int ch = lc4 + c4;
                cp16(sb + AT_SH + swz(lrow, ch), gs + ch * 8);
            }
        }
    }
    CP_COMMIT(); CP_WAIT0(); __syncthreads();

    // ---- stage 1: A = causal(q k^T) -> AH fp16 ----
    {
        const int wm1 = wid >> 2, wn1 = wid & 3;
        if (wm1 == 0 && wn1 >= 2) {
            // wholly above diagonal: zero AH rows 0..63, chunks 8..15 (cols 64..127)
            int row = (wn1 - 2) * 32 + lane;
            uint4 zz = make_uint4(0, 0, 0, 0);
#pragma unroll
            for (int cc8 = 0; cc8 < 8; cc8++)
                *(uint4*)(smem + AT_AH + row * 256 + 128 + cc8 * 16) = zz;
        } else {
            float acc1[4][4][4];
#pragma unroll
            for (int i = 0; i < 4; i++)
#pragma unroll
                for (int j = 0; j < 4; j++)
#pragma unroll
                    for (int r = 0; r < 4; r++) acc1[i][j][r] = 0.f;

#pragma unroll
            for (int ks = 0; ks < 4; ks++) {
                const int c0 = ks * 2;
                uint32_t a[4][4], b[8];
#pragma unroll
                for (int i = 0; i < 4; i++)
                    ldsm4(a[i], sb + AT_QH + swz(64 * wm1 + 16 * i + a_row, c0 + a_cofs));
#pragma unroll
                for (int jp = 0; jp < 2; jp++)
                    ldsm4(&b[jp * 4], sb + AT_KH + swz(32 * wn1 + 16 * jp + b_row0, c0 + b_cofs));
#pragma unroll
                for (int i = 0; i < 4; i++)
#pragma unroll
                    for (int j = 0; j < 4; j++)
                        mma16816h(acc1[i][j], a[i], &b[j * 2]);
            }
            // causal mask + fp16 store to AH
#pragma unroll
            for (int i = 0; i < 4; i++) {
                int r0 = 64 * wm1 + 16 * i + g;
#pragma unroll
                for (int j = 0; j < 4; j++) {
                    int cb = 32 * wn1 + 8 * j + 2 * tg;
                    int ch = cb >> 3;
                    float v0 = (cb     <= r0) ? acc1[i][j][0] : 0.f;
                    float v1 = (cb + 1 <= r0) ? acc1[i][j][1] : 0.f;
                    *(__half2*)(smem + AT_AH + swzA(r0, ch) + (cb & 7) * 2) =
                        __floats2half2_rn(v0, v1);
                    int r1 = r0 + 8;
                    float v2 = (cb     <= r1) ? acc1[i][j][2] : 0.f;
                    float v3 = (cb + 1 <= r1) ? acc1[i][j][3] : 0.f;
                    *(__half2*)(smem + AT_AH + swzA(r1, ch) + (cb & 7) * 2) =
                        __floats2half2_rn(v2, v3);
                }
            }
        }
    }
    __syncthreads();

    // ---- stage 2: o = q @ S_excl + A @ v ----
    const int wm2 = wid >> 1;    // m32 block
    const int wn2 = wid & 1;     // n32 block
    float o2[2][4][4];
#pragma unroll
    for (int i = 0; i < 2; i++)
#pragma unroll
        for (int j = 0; j < 4; j++)
#pragma unroll
            for (int r = 0; r < 4; r++) o2[i][j][r] = 0.f;

    // q @ S (k-dim = 64)
#pragma unroll
    for (int ks = 0; ks < 4; ks++) {
        const int c0 = ks * 2, d0 = ks * 16;
        uint32_t a[2][4], b[8];
#pragma unroll
        for (int i = 0; i < 2; i++)
            ldsm4(a[i], sb + AT_QH + swz(32 * wm2 + 16 * i + a_row, c0 + a_cofs));
#pragma unroll
        for (int jp = 0; jp < 2; jp++)
            ldsm4t(&b[jp * 4], sb + AT_SH + swz(d0 + tb_krow, 4 * wn2 + 2 * jp + tb_nch));
#pragma unroll
        for (int i = 0; i < 2; i++)
#pragma unroll
            for (int j = 0; j < 4; j++)
                mma16816h(o2[i][j], a[i], &b[j * 2]);
    }
    // A @ v (triangular: s < 32*(wm2+1))
    const int nkt = 2 * (wm2 + 1);
    for (int kt = 0; kt < nkt; kt++) {
        const int s0 = kt * 16;
        uint32_t a[2][4], b[8];
#pragma unroll
        for (int i = 0; i < 2; i++)
            ldsm4(a[i], sb + AT_AH + swzA(32 * wm2 + 16 * i + a_row, 2 * kt + a_cofs));
#pragma unroll
        for (int jp = 0; jp < 2; jp++)
            ldsm4t(&b[jp * 4], sb + AT_VH + swz(s0 + tb_krow, 4 * wn2 + 2 * jp + tb_nch));
#pragma unroll
        for (int i = 0; i < 2; i++)
#pragma unroll
            for (int j = 0; j < 4; j++)
                mma16816h(o2[i][j], a[i], &b[j * 2]);
    }

    // store fp32
#pragma unroll
    for (int i = 0; i < 2; i++) {
        int row = 32 * wm2 + 16 * i + g;
#pragma unroll
        for (int j = 0; j < 4; j++) {
            int col = 32 * wn2 + 8 * j + 2 * tg;
            *(float2*)&out[base + (size_t)row * DIM + col] =
                make_float2(o2[i][j][0], o2[i][j][1]);
            *(float2*)&out[base + (size_t)(row + 8) * DIM + col] =
                make_float2(o2[i][j][2], o2[i][j][3]);
        }
    }
}

// ---------------------------------------------------------------------------
extern "C" void kernel_launch(void* const* d_in, const int* in_sizes, int n_in,
                              void* d_out, int out_size)
{
    const float* query = (const float*)d_in[0];
    const float* key   = (const float*)d_in[1];
    const float* Wq    = (const float*)d_in[2];
    const float* Wk    = (const float*)d_in[3];
    const float* Wv    = (const float*)d_in[4];
    float* out = (float*)d_out;

    cudaFuncSetAttribute(proj_hmma, cudaFuncAttributeMaxDynamicSharedMemorySize, SMEM_TOTAL);
    cudaFuncSetAttribute(chunk_kv, cudaFuncAttributeMaxDynamicSharedMemorySize, 32768);
    cudaFuncSetAttribute(attn_out, cudaFuncAttributeMaxDynamicSharedMemorySize, AT_BYTES);

    // 1. fp16 conversion
    conv_split<<<dim3(256, 5), 256>>>(query, key, Wq, Wk, Wv);

    // 2. projections (fp16 HMMA, fused softmax, fp16 output)
    proj_hmma<<<dim3(8, 32, 3), 256, SMEM_TOTAL>>>();

    // 3. chunked causal linear attention, all on HMMA
    dim3 agrid(NCHK, NBATCH * NH);
    chunk_kv<<<agrid, 256, 32768>>>();
    prefix_kv<<<NBATCH * NH * 8, 512>>>();
    attn_out<<<agrid, 256, AT_BYTES>>>(out);
}

// round 14
// speedup vs baseline: 3.6245x; 1.0105x over previous
#include <cuda_runtime.h>
#include <cuda_fp16.h>
#include <cstdint>
#include <cstddef>

// ---------------- problem constants ----------------
#define NBATCH 2
#define LSEQ   2048
#define DIM    1024
#define NH     16
#define DH     64
#define CHK    128
#define NCHK   (LSEQ / CHK)      // 16
#define MROWS  (NBATCH * LSEQ)   // 4096

// ---------------- device scratch (no allocs allowed) ----------------
__device__ __align__(16) __half g_Xh[2][MROWS * DIM];    // fp16 inputs (q,k)
__device__ __align__(16) __half g_Wh[3][DIM * DIM];      // fp16 weights
__device__ __align__(16) __half g_Oh[3][MROWS * DIM];    // fp16 projected Q,K,V
__device__ __align__(16) __half g_Ph[NBATCH * NH * NCHK * DH * DH];  // chunk sums fp16
__device__ __align__(16) __half g_Sh[NBATCH * NH * NCHK * DH * DH];  // excl prefix fp16

// ---------------- small helpers ----------------
__device__ __forceinline__ uint32_t smem_u32(const void* p) {
    uint32_t a;
    asm("{ .reg .u64 t; cvta.to.shared.u64 t, %1; cvt.u32.u64 %0, t; }" : "=r"(a) : "l"(p));
    return a;
}
__device__ __forceinline__ void cp16(uint32_t s, const void* g) {
    asm volatile("cp.async.cg.shared.global [%0], [%1], 16;" :: "r"(s), "l"(g));
}
#define CP_COMMIT() asm volatile("cp.async.commit_group;" ::: "memory")
#define CP_WAIT1()  asm volatile("cp.async.wait_group 1;" ::: "memory")
#define CP_WAIT0()  asm volatile("cp.async.wait_group 0;" ::: "memory")

__device__ __forceinline__ void mma16816h(float* c, const uint32_t* a, const uint32_t* b) {
    asm volatile(
        "mma.sync.aligned.m16n8k16.row.col.f32.f16.f16.f32 "
        "{%0,%1,%2,%3}, {%4,%5,%6,%7}, {%8,%9}, {%0,%1,%2,%3};"
        : "+f"(c[0]), "+f"(c[1]), "+f"(c[2]), "+f"(c[3])
        : "r"(a[0]), "r"(a[1]), "r"(a[2]), "r"(a[3]), "r"(b[0]), "r"(b[1]));
}
__device__ __forceinline__ void ldsm4(uint32_t* r, uint32_t addr) {
    asm volatile("ldmatrix.sync.aligned.m8n8.x4.shared.b16 {%0,%1,%2,%3}, [%4];"
                 : "=r"(r[0]), "=r"(r[1]), "=r"(r[2]), "=r"(r[3]) : "r"(addr));
}
__device__ __forceinline__ void ldsm4t(uint32_t* r, uint32_t addr) {
    asm volatile("ldmatrix.sync.aligned.m8n8.x4.trans.shared.b16 {%0,%1,%2,%3}, [%4];"
                 : "=r"(r[0]), "=r"(r[1]), "=r"(r[2]), "=r"(r[3]) : "r"(addr));
}

// swizzled byte offset: 128B-pitch rows, 16B chunk c (0..7)
__device__ __forceinline__ uint32_t swz(int row, int c) {
    return (uint32_t)(row * 128 + ((c ^ (row & 7)) << 4));
}
// 256B-pitch rows, 16 chunks: XOR low 3 bits only
__device__ __forceinline__ uint32_t swzA(int row, int c) {
    return (uint32_t)(row * 256 + (((c & 8) | ((c & 7) ^ (row & 7))) << 4));
}

// ---------------- fp16 conversion ----------------
__global__ __launch_bounds__(256)
void conv_split(const float* __restrict__ q, const float* __restrict__ k,
                const float* __restrict__ wq, const float* __restrict__ wk,
                const float* __restrict__ wv)
{
    int y = blockIdx.y;
    const float* src;
    __half* dst;
    int n;
    switch (y) {
        case 0: src = q;  dst = g_Xh[0]; n = MROWS * DIM; break;
        case 1: src = k;  dst = g_Xh[1]; n = MROWS * DIM; break;
        case 2: src = wq; dst = g_Wh[0]; n = DIM * DIM;   break;
        case 3: src = wk; dst = g_Wh[1]; n = DIM * DIM;   break;
        default: src = wv; dst = g_Wh[2]; n = DIM * DIM;  break;
    }
    int n4 = n >> 2;
    for (int i = blockIdx.x * blockDim.x + threadIdx.x; i < n4;
         i += gridDim.x * blockDim.x) {
        float4 f = ((const float4*)src)[i];
        ushort4 u = make_ushort4(
            __half_as_ushort(__float2half(f.x)), __half_as_ushort(__float2half(f.y)),
            __half_as_ushort(__float2half(f.z)), __half_as_ushort(__float2half(f.w)));
        ((ushort4*)dst)[i] = u;
    }
}

// ---------------- HMMA projection GEMM (+ fused softmax, fp16 out) ----------------
#define STAGE_BYTES 32768
#define SMEM_TOTAL  (3 * STAGE_BYTES)

__global__ __launch_bounds__(256, 2)
void proj_hmma()
{
    extern __shared__ char smem[];
    const uint32_t sb = smem_u32(smem);

    const int tid = threadIdx.x;
    const int wid = tid >> 5;
    const int lane = tid & 31;
    const int wm = wid >> 2;
    const int wn = wid & 3;
    const int z = blockIdx.z;

    const __half* __restrict__ A = g_Xh[z ? 1 : 0];
    const __half* __restrict__ B = g_Wh[z];
    __half* __restrict__ Out = g_Oh[z];

    const int m0 = blockIdx.y * 128;
    const int n0 = blockIdx.x * 128;

    float acc[4][4][4];
#pragma unroll
    for (int i = 0; i < 4; i++)
#pragma unroll
        for (int j = 0; j < 4; j++)
#pragma unroll
            for (int r = 0; r < 4; r++) acc[i][j][r] = 0.f;

    const int lrow = tid >> 1;
    const int lc4  = (tid & 1) * 4;
    auto load_tile = [&](int kk, int stg) {
        const int k0 = kk * 64;
        const uint32_t sa = sb + stg * STAGE_BYTES;
        const uint32_t sbB = sa + 16384;
        const __half* ga = A + (size_t)(m0 + lrow) * DIM + k0 + lc4 * 8;
        const __half* gb = B + (size_t)(n0 + lrow) * DIM + k0 + lc4 * 8;
#pragma unroll
        for (int c = 0; c < 4; c++) {
            cp16(sa  + swz(lrow, lc4 + c), ga + c * 8);
            cp16(sbB + swz(lrow, lc4 + c), gb + c * 8);
        }
    };

    const int a_row = (lane & 7) + ((lane >> 3) & 1) * 8;
    const int a_cofs = lane >> 4;
    const int b_row0 = ((lane >> 4) & 1) * 8 + (lane & 7);
    const int b_cofs = (lane >> 3) & 1;

    load_tile(0, 0); CP_COMMIT();
    load_tile(1, 1); CP_COMMIT();

    for (int kk = 0; kk < 16; kk++) {
        const int stg = kk % 3;
        CP_WAIT1();
        __syncthreads();
        if (kk + 2 < 16) { load_tile(kk + 2, (kk + 2) % 3); CP_COMMIT(); }

        const uint32_t sa = sb + stg * STAGE_BYTES;
        const uint32_t sbB = sa + 16384;

#pragma unroll
        for (int ks = 0; ks < 4; ks++) {
            const int c0 = ks * 2;
            uint32_t a[4][4], b[8];
#pragma unroll
            for (int i = 0; i < 4; i++)
                ldsm4(a[i], sa + swz(wm * 64 + i * 16 + a_row, c0 + a_cofs));
#pragma unroll
            for (int jp = 0; jp < 2; jp++)
                ldsm4(&b[jp * 4], sbB + swz(wn * 32 + jp * 16 + b_row0, c0 + b_cofs));
#pragma unroll
            for (int i = 0; i < 4; i++)
#pragma unroll
                for (int j = 0; j < 4; j++)
                    mma16816h(acc[i][j], a[i], &b[j * 2]);
        }
    }

    const int g = lane >> 2;
    const int tg = lane & 3;
    __syncthreads();

    if (z < 2) {
        float* red = (float*)smem;
        const int seg = wn >> 1;
        const int pr = wn & 1;

        float ml[4][2];
#pragma unroll
        for (int i = 0; i < 4; i++)
#pragma unroll
            for (int h = 0; h < 2; h++) {
                float m = acc[i][0][h * 2];
#pragma unroll
                for (int j = 0; j < 4; j++) {
                    m = fmaxf(m, acc[i][j][h * 2]);
                    m = fmaxf(m, acc[i][j][h * 2 + 1]);
                }
                m = fmaxf(m, __shfl_xor_sync(0xffffffffu, m, 1));
                m = fmaxf(m, __shfl_xor_sync(0xffffffffu, m, 2));
                ml[i][h] = m;
            }
        if (tg == 0) {
#pragma unroll
            for (int i = 0; i < 4; i++)
#pragma unroll
                for (int h = 0; h < 2; h++) {
                    int row = wm * 64 + i * 16 + h * 8 + g;
                    red[(row * 2 + seg) * 2 + pr] = ml[i][h];
                }
        }
        __syncthreads();
        float mseg[4][2];
#pragma unroll
        for (int i = 0; i < 4; i++)
#pragma unroll
            for (int h = 0; h < 2; h++) {
                int row = wm * 64 + i * 16 + h * 8 + g;
                mseg[i][h] = fmaxf(red[(row * 2 + seg) * 2 + 0],
                                   red[(row * 2 + seg) * 2 + 1]);
            }
        __syncthreads();

        float sl[4][2];
#pragma unroll
        for (int i = 0; i < 4; i++)
#pragma unroll
            for (int h = 0; h < 2; h++) {
                float s = 0.f;
#pragma unroll
                for (int j = 0; j < 4; j++) {
                    float e0 = __expf(acc[i][j][h * 2]     - mseg[i][h]);
                    float e1 = __expf(acc[i][j][h * 2 + 1] - mseg[i][h]);
                    acc[i][j][h * 2] = e0; acc[i][j][h * 2 + 1] = e1;
                    s += e0 + e1;
                }
                s += __shfl_xor_sync(0xffffffffu, s, 1);
                s += __shfl_xor_sync(0xffffffffu, s, 2);
                sl[i][h] = s;
            }
        if (tg == 0) {
#pragma unroll
            for (int i = 0; i < 4; i++)
#pragma unroll
                for (int h = 0; h < 2; h++) {
                    int row = wm * 64 + i * 16 + h * 8 + g;
                    red[(row * 2 + seg) * 2 + pr] = sl[i][h];
                }
        }
        __syncthreads();
#pragma unroll
        for (int i = 0; i < 4; i++)
#pragma unroll
            for (int h = 0; h < 2; h++) {
                int row = wm * 64 + i * 16 + h * 8 + g;
                float inv = 1.0f / (red[(row * 2 + seg) * 2 + 0] +
                                    red[(row * 2 + seg) * 2 + 1]);
#pragma unroll
                for (int j = 0; j < 4; j++) {
                    acc[i][j][h * 2]     *= inv;
                    acc[i][j][h * 2 + 1] *= inv;
                }
            }
    }

    // store fp16
#pragma unroll
    for (int i = 0; i < 4; i++) {
        const int r0 = m0 + wm * 64 + i * 16 + g;
#pragma unroll
        for (int j = 0; j < 4; j++) {
            const int cc = n0 + wn * 32 + j * 8 + tg * 2;
            *(__half2*)&Out[(size_t)r0 * DIM + cc] =
                __floats2half2_rn(acc[i][j][0], acc[i][j][1]);
            *(__half2*)&Out[(size_t)(r0 + 8) * DIM + cc] =
                __floats2half2_rn(acc[i][j][2], acc[i][j][3]);
        }
    }
}

// ---------------- per-chunk KV sums on HMMA: P = k^T v (64x64x128) ----------------
__global__ __launch_bounds__(256)
void chunk_kv()
{
    extern __shared__ char smem[];
    const uint32_t sb = smem_u32(smem);   // KH @0 (16KB), VH @16384 (16KB)

    const int c = blockIdx.x;
    const int nh = blockIdx.y;
    const int n = nh >> 4, h = nh & 15;
    const size_t base = ((size_t)(n * LSEQ + c * CHK)) * DIM + h * DH;
    const int tid = threadIdx.x;
    const int lane = tid & 31;
    const int wid = tid >> 5;

    {
        int lrow = tid >> 1, lc4 = (tid & 1) * 4;
        const __half* gk = g_Oh[1] + base + (size_t)lrow * DIM;
        const __half* gv = g_Oh[2] + base + (size_t)lrow * DIM;
#pragma unroll
        for (int c4 = 0; c4 < 4; c4++) {
            cp16(sb + swz(lrow, lc4 + c4), gk + (lc4 + c4) * 8);
            cp16(sb + 16384 + swz(lrow, lc4 + c4), gv + (lc4 + c4) * 8);
        }
    }
    CP_COMMIT(); CP_WAIT0(); __syncthreads();

    const int wmc = wid >> 1;    // d1 block (m16)
    const int wnc = wid & 1;     // d2 block (n32)
    const int ta_krow = ((lane >> 4) << 3) + (lane & 7);
    const int ta_mch  = (lane >> 3) & 1;
    const int tb_krow = (((lane >> 3) & 1) << 3) + (lane & 7);
    const int tb_nch  = lane >> 4;

    float acc[4][4];
#pragma unroll
    for (int j = 0; j < 4; j++)
#pragma unroll
        for (int r = 0; r < 4; r++) acc[j][r] = 0.f;

#pragma unroll
    for (int kt = 0; kt < 8; kt++) {
        const int t0 = kt * 16;
        uint32_t a[4], b[8];
        ldsm4t(a, sb + swz(t0 + ta_krow, 2 * wmc + ta_mch));
#pragma unroll
        for (int jp = 0; jp < 2; jp++)
            ldsm4t(&b[jp * 4], sb + 16384 + swz(t0 + tb_krow, 4 * wnc + 2 * jp + tb_nch));
#pragma unroll
        for (int j = 0; j < 4; j++)
            mma16816h(acc[j], a, &b[j * 2]);
    }

    const int g = lane >> 2, tg = lane & 3;
    __half* P = g_Ph + ((size_t)nh * NCHK + c) * (DH * DH);
#pragma unroll
    for (int j = 0; j < 4; j++) {
        int row = 16 * wmc + g;
        int col = 32 * wnc + 8 * j + 2 * tg;
        *(__half2*)&P[row * 64 + col] = __floats2half2_rn(acc[j][0], acc[j][1]);
        *(__half2*)&P[(row + 8) * 64 + col] = __floats2half2_rn(acc[j][2], acc[j][3]);
    }
}

// ---------------- exclusive prefix: fp16 in, fp32 accum, fp16 out ----------------
// grid: (NB*NH) * 4 slabs, 512 threads; one half2 lane per thread.
__global__ __launch_bounds__(512)
void prefix_kv()
{
    const int nh = blockIdx.x >> 2;
    const int slab = blockIdx.x & 3;
    const __half2* P = (const __half2*)(g_Ph + (size_t)nh * NCHK * (DH * DH));
    __half2* S = (__half2*)(g_Sh + (size_t)nh * NCHK * (DH * DH));
    const int idx = slab * 512 + threadIdx.x;   // 0..2047 half2 lanes
    float rx = 0.f, ry = 0.f;
#pragma unroll
    for (int c = 0; c < NCHK; c++) {
        S[c * 2048 + idx] = __floats2half2_rn(rx, ry);
        float2 t = __half22float2(P[c * 2048 + idx]);
        rx += t.x; ry += t.y;
    }
}

// ---------------- attention output on HMMA ----------------
// smem: QH 16K @0, KH 16K @16384, VH 16K @32768, SH 8K @49152, AH 32K @57344
#define AT_QH 0
#define AT_KH 16384
#define AT_VH 32768
#define AT_SH 49152
#define AT_AH 57344
#define AT_BYTES (AT_AH + 32768)   // 90112

__global__ __launch_bounds__(256, 2)
void attn_out(float* __restrict__ out)
{
    extern __shared__ char smem[];
    const uint32_t sb = smem_u32(smem);

    const int c = blockIdx.x;
    const int nh = blockIdx.y;
    const int n = nh >> 4, h = nh & 15;
    const size_t base = ((size_t)(n * LSEQ + c * CHK)) * DIM + h * DH;
    const int tid = threadIdx.x;
    const int lane = tid & 31;
    const int wid = tid >> 5;
    const int g = lane >> 2, tg = lane & 3;

    const int a_row = (lane & 7) + ((lane >> 3) & 1) * 8;
    const int a_cofs = lane >> 4;
    const int b_row0 = ((lane >> 4) & 1) * 8 + (lane & 7);
    const int b_cofs = (lane >> 3) & 1;
    const int tb_krow = (((lane >> 3) & 1) << 3) + (lane & 7);
    const int tb_nch  = lane >> 4;

    // ---- load QH/KH/VH (128 rows) + SH (64 rows, only if c>0) ----
    {
        int lrow = tid >> 1, lc4 = (tid & 1) * 4;
        const __half* gq = g_Oh[0] + base + (size_t)lrow * DIM;
        const __half* gk = g_Oh[1] + base + (size_t)lrow * DIM;
        const __half* gv = g_Oh[2] + base + (size_t)lrow * DIM;
#pragma unroll
        for (int c4 = 0; c4 < 4; c4++) {
            int ch = lc4 + c4;
            cp16(sb + AT_QH + swz(lrow, ch), gq + ch * 8);
            cp16(sb + AT_KH + swz(lrow, ch), gk + ch * 8);
            cp16(sb + AT_VH + swz(lrow, ch), gv + ch * 8);
        }
        if (c > 0 && tid < 128) {
            const __half* gs = g_Sh + ((size_t)nh * NCHK + c) * (DH * DH) + lrow * 64;
#pragma unroll
            for (int c4 = 0; c4 < 4; c4++) {
                int ch = lc4 + c4;
                cp16(sb + AT_SH + swz(lrow, ch), gs + ch * 8);
            }
        }
    }
    CP_COMMIT(); CP_WAIT0(); __syncthreads();

    // ---- stage 1: A = causal(q k^T) -> AH fp16 ----
    {
        const int wm1 = wid >> 2, wn1 = wid & 3;
        if (wm1 == 0 && wn1 >= 2) {
            int row = (wn1 - 2) * 32 + lane;
            uint4 zz = make_uint4(0, 0, 0, 0);
#pragma unroll
            for (int cc8 = 0; cc8 < 8; cc8++)
                *(uint4*)(smem + AT_AH + row * 256 + 128 + cc8 * 16) = zz;
        } else {
            float acc1[4][4][4];
#pragma unroll
            for (int i = 0; i < 4; i++)
#pragma unroll
                for (int j = 0; j < 4; j++)
#pragma unroll
                    for (int r = 0; r < 4; r++) acc1[i][j][r] = 0.f;

#pragma unroll
            for (int ks = 0; ks < 4; ks++) {
                const int c0 = ks * 2;
                uint32_t a[4][4], b[8];
#pragma unroll
                for (int i = 0; i < 4; i++)
                    ldsm4(a[i], sb + AT_QH + swz(64 * wm1 + 16 * i + a_row, c0 + a_cofs));
#pragma unroll
                for (int jp = 0; jp < 2; jp++)
                    ldsm4(&b[jp * 4], sb + AT_KH + swz(32 * wn1 + 16 * jp + b_row0, c0 + b_cofs));
#pragma unroll
                for (int i = 0; i < 4; i++)
#pragma unroll
                    for (int j = 0; j < 4; j++)
                        mma16816h(acc1[i][j], a[i], &b[j * 2]);
            }
#pragma unroll
            for (int i = 0; i < 4; i++) {
                int r0 = 64 * wm1 + 16 * i + g;
#pragma unroll
                for (int j = 0; j < 4; j++) {
                    int cb = 32 * wn1 + 8 * j + 2 * tg;
                    int ch = cb >> 3;
                    float v0 = (cb     <= r0) ? acc1[i][j][0] : 0.f;
                    float v1 = (cb + 1 <= r0) ? acc1[i][j][1] : 0.f;
                    *(__half2*)(smem + AT_AH + swzA(r0, ch) + (cb & 7) * 2) =
                        __floats2half2_rn(v0, v1);
                    int r1 = r0 + 8;
                    float v2 = (cb     <= r1) ? acc1[i][j][2] : 0.f;
                    float v3 = (cb + 1 <= r1) ? acc1[i][j][3] : 0.f;
                    *(__half2*)(smem + AT_AH + swzA(r1, ch) + (cb & 7) * 2) =
                        __floats2half2_rn(v2, v3);
                }
            }
        }
    }
    __syncthreads();

    // ---- stage 2: o = q @ S_excl + A @ v ----
    const int wm2 = wid >> 1;
    const int wn2 = wid & 1;
    float o2[2][4][4];
#pragma unroll
    for (int i = 0; i < 2; i++)
#pragma unroll
        for (int j = 0; j < 4; j++)
#pragma unroll
            for (int r = 0; r < 4; r++) o2[i][j][r] = 0.f;

    if (c > 0) {
#pragma unroll
        for (int ks = 0; ks < 4; ks++) {
            const int c0 = ks * 2, d0 = ks * 16;
            uint32_t a[2][4], b[8];
#pragma unroll
            for (int i = 0; i < 2; i++)
                ldsm4(a[i], sb + AT_QH + swz(32 * wm2 + 16 * i + a_row, c0 + a_cofs));
#pragma unroll
            for (int jp = 0; jp < 2; jp++)
                ldsm4t(&b[jp * 4], sb + AT_SH + swz(d0 + tb_krow, 4 * wn2 + 2 * jp + tb_nch));
#pragma unroll
            for (int i = 0; i < 2; i++)
#pragma unroll
                for (int j = 0; j < 4; j++)
                    mma16816h(o2[i][j], a[i], &b[j * 2]);
        }
    }
    const int nkt = 2 * (wm2 + 1);
    for (int kt = 0; kt < nkt; kt++) {
        const int s0 = kt * 16;
        uint32_t a[2][4], b[8];
#pragma unroll
        for (int i = 0; i < 2; i++)
            ldsm4(a[i], sb + AT_AH + swzA(32 * wm2 + 16 * i + a_row, 2 * kt + a_cofs));
#pragma unroll
        for (int jp = 0; jp < 2; jp++)
            ldsm4t(&b[jp * 4], sb + AT_VH + swz(s0 + tb_krow, 4 * wn2 + 2 * jp + tb_nch));
#pragma unroll
        for (int i = 0; i < 2; i++)
#pragma unroll
            for (int j = 0; j < 4; j++)
                mma16816h(o2[i][j], a[i], &b[j * 2]);
    }

#pragma unroll
    for (int i = 0; i < 2; i++) {
        int row = 32 * wm2 + 16 * i + g;
#pragma unroll
        for (int j = 0; j < 4; j++) {
            int col = 32 * wn2 + 8 * j + 2 * tg;
            *(float2*)&out[base + (size_t)row * DIM + col] =
                make_float2(o2[i][j][0], o2[i][j][1]);
            *(float2*)&out[base + (size_t)(row + 8) * DIM + col] =
                make_float2(o2[i][j][2], o2[i][j][3]);
        }
    }
}

// ---------------------------------------------------------------------------
extern "C" void kernel_launch(void* const* d_in, const int* in_sizes, int n_in,
                              void* d_out, int out_size)
{
    const float* query = (const float*)d_in[0];
    const float* key   = (const float*)d_in[1];
    const float* Wq    = (const float*)d_in[2];
    const float* Wk    = (const float*)d_in[3];
    const float* Wv    = (const float*)d_in[4];
    float* out = (float*)d_out;

    cudaFuncSetAttribute(proj_hmma, cudaFuncAttributeMaxDynamicSharedMemorySize, SMEM_TOTAL);
    cudaFuncSetAttribute(chunk_kv, cudaFuncAttributeMaxDynamicSharedMemorySize, 32768);
    cudaFuncSetAttribute(attn_out, cudaFuncAttributeMaxDynamicSharedMemorySize, AT_BYTES);

    // 1. fp16 conversion
    conv_split<<<dim3(384, 5), 256>>>(query, key, Wq, Wk, Wv);

    // 2. projections (fp16 HMMA, fused softmax, fp16 output)
    proj_hmma<<<dim3(8, 32, 3), 256, SMEM_TOTAL>>>();

    // 3. chunked causal linear attention, all on HMMA
    dim3 agrid(NCHK, NBATCH * NH);
    chunk_kv<<<agrid, 256, 32768>>>();
    prefix_kv<<<NBATCH * NH * 4, 512>>>();
    attn_out<<<agrid, 256, AT_BYTES>>>(out);
}

// round 15
// speedup vs baseline: 3.7317x; 1.0296x over previous
#include <cuda_runtime.h>
#include <cuda_fp16.h>
#include <cstdint>
#include <cstddef>

// ---------------- problem constants ----------------
#define NBATCH 2
#define LSEQ   2048
#define DIM    1024
#define NH     16
#define DH     64
#define CHK    128
#define NCHK   (LSEQ / CHK)      // 16
#define MROWS  (NBATCH * LSEQ)   // 4096

// ---------------- device scratch (no allocs allowed) ----------------
__device__ __align__(16) __half g_Xh[2][MROWS * DIM];    // fp16 inputs (q,k)
__device__ __align__(16) __half g_Wh[3][DIM * DIM];      // fp16 weights
__device__ __align__(16) __half g_Oh[3][MROWS * DIM];    // fp16 projected Q,K,V
__device__ __align__(16) __half g_Ph[NBATCH * NH * NCHK * DH * DH];  // chunk sums fp16
__device__ __align__(16) __half g_Sh[NBATCH * NH * NCHK * DH * DH];  // excl prefix fp16

// ---------------- small helpers ----------------
__device__ __forceinline__ uint32_t smem_u32(const void* p) {
    uint32_t a;
    asm("{ .reg .u64 t; cvta.to.shared.u64 t, %1; cvt.u32.u64 %0, t; }" : "=r"(a) : "l"(p));
    return a;
}
__device__ __forceinline__ void cp16(uint32_t s, const void* g) {
    asm volatile("cp.async.cg.shared.global [%0], [%1], 16;" :: "r"(s), "l"(g));
}
#define CP_COMMIT() asm volatile("cp.async.commit_group;" ::: "memory")
#define CP_WAIT1()  asm volatile("cp.async.wait_group 1;" ::: "memory")
#define CP_WAIT0()  asm volatile("cp.async.wait_group 0;" ::: "memory")

__device__ __forceinline__ void mma16816h(float* c, const uint32_t* a, const uint32_t* b) {
    asm volatile(
        "mma.sync.aligned.m16n8k16.row.col.f32.f16.f16.f32 "
        "{%0,%1,%2,%3}, {%4,%5,%6,%7}, {%8,%9}, {%0,%1,%2,%3};"
        : "+f"(c[0]), "+f"(c[1]), "+f"(c[2]), "+f"(c[3])
        : "r"(a[0]), "r"(a[1]), "r"(a[2]), "r"(a[3]), "r"(b[0]), "r"(b[1]));
}
__device__ __forceinline__ void ldsm4(uint32_t* r, uint32_t addr) {
    asm volatile("ldmatrix.sync.aligned.m8n8.x4.shared.b16 {%0,%1,%2,%3}, [%4];"
                 : "=r"(r[0]), "=r"(r[1]), "=r"(r[2]), "=r"(r[3]) : "r"(addr));
}
__device__ __forceinline__ void ldsm4t(uint32_t* r, uint32_t addr) {
    asm volatile("ldmatrix.sync.aligned.m8n8.x4.trans.shared.b16 {%0,%1,%2,%3}, [%4];"
                 : "=r"(r[0]), "=r"(r[1]), "=r"(r[2]), "=r"(r[3]) : "r"(addr));
}

// swizzled byte offset: 128B-pitch rows, 16B chunk c (0..7)
__device__ __forceinline__ uint32_t swz(int row, int c) {
    return (uint32_t)(row * 128 + ((c ^ (row & 7)) << 4));
}
// 256B-pitch rows, 16 chunks: XOR low 3 bits only
__device__ __forceinline__ uint32_t swzA(int row, int c) {
    return (uint32_t)(row * 256 + (((c & 8) | ((c & 7) ^ (row & 7))) << 4));
}

// ---------------- fp16 conversion ----------------
__global__ __launch_bounds__(256)
void conv_split(const float* __restrict__ q, const float* __restrict__ k,
                const float* __restrict__ wq, const float* __restrict__ wk,
                const float* __restrict__ wv)
{
    int y = blockIdx.y;
    const float* src;
    __half* dst;
    int n;
    switch (y) {
        case 0: src = q;  dst = g_Xh[0]; n = MROWS * DIM; break;
        case 1: src = k;  dst = g_Xh[1]; n = MROWS * DIM; break;
        case 2: src = wq; dst = g_Wh[0]; n = DIM * DIM;   break;
        case 3: src = wk; dst = g_Wh[1]; n = DIM * DIM;   break;
        default: src = wv; dst = g_Wh[2]; n = DIM * DIM;  break;
    }
    int n4 = n >> 2;
    for (int i = blockIdx.x * blockDim.x + threadIdx.x; i < n4;
         i += gridDim.x * blockDim.x) {
        float4 f = ((const float4*)src)[i];
        ushort4 u = make_ushort4(
            __half_as_ushort(__float2half(f.x)), __half_as_ushort(__float2half(f.y)),
            __half_as_ushort(__float2half(f.z)), __half_as_ushort(__float2half(f.w)));
        ((ushort4*)dst)[i] = u;
    }
}

// ---------------- HMMA projection GEMM (+ fused softmax, fp16 out) ----------------
#define STAGE_BYTES 32768
#define SMEM_TOTAL  (3 * STAGE_BYTES)

__global__ __launch_bounds__(256, 2)
void proj_hmma()
{
    extern __shared__ char smem[];
    const uint32_t sb = smem_u32(smem);

    const int tid = threadIdx.x;
    const int wid = tid >> 5;
    const int lane = tid & 31;
    const int wm = wid >> 2;
    const int wn = wid & 3;
    const int z = blockIdx.z;

    const __half* __restrict__ A = g_Xh[z ? 1 : 0];
    const __half* __restrict__ B = g_Wh[z];
    __half* __restrict__ Out = g_Oh[z];

    const int m0 = blockIdx.y * 128;
    const int n0 = blockIdx.x * 128;

    float acc[4][4][4];
#pragma unroll
    for (int i = 0; i < 4; i++)
#pragma unroll
        for (int j = 0; j < 4; j++)
#pragma unroll
            for (int r = 0; r < 4; r++) acc[i][j][r] = 0.f;

    const int lrow = tid >> 1;
    const int lc4  = (tid & 1) * 4;
    auto load_tile = [&](int kk, int stg) {
        const int k0 = kk * 64;
        const uint32_t sa = sb + stg * STAGE_BYTES;
        const uint32_t sbB = sa + 16384;
        const __half* ga = A + (size_t)(m0 + lrow) * DIM + k0 + lc4 * 8;
        const __half* gb = B + (size_t)(n0 + lrow) * DIM + k0 + lc4 * 8;
#pragma unroll
        for (int c = 0; c < 4; c++) {
            cp16(sa  + swz(lrow, lc4 + c), ga + c * 8);
            cp16(sbB + swz(lrow, lc4 + c), gb + c * 8);
        }
    };

    const int a_row = (lane & 7) + ((lane >> 3) & 1) * 8;
    const int a_cofs = lane >> 4;
    const int b_row0 = ((lane >> 4) & 1) * 8 + (lane & 7);
    const int b_cofs = (lane >> 3) & 1;

    load_tile(0, 0); CP_COMMIT();
    load_tile(1, 1); CP_COMMIT();

    for (int kk = 0; kk < 16; kk++) {
        const int stg = kk % 3;
        CP_WAIT1();
        __syncthreads();
        if (kk + 2 < 16) { load_tile(kk + 2, (kk + 2) % 3); CP_COMMIT(); }

        const uint32_t sa = sb + stg * STAGE_BYTES;
        const uint32_t sbB = sa + 16384;

#pragma unroll
        for (int ks = 0; ks < 4; ks++) {
            const int c0 = ks * 2;
            uint32_t a[4][4], b[8];
#pragma unroll
            for (int i = 0; i < 4; i++)
                ldsm4(a[i], sa + swz(wm * 64 + i * 16 + a_row, c0 + a_cofs));
#pragma unroll
            for (int jp = 0; jp < 2; jp++)
                ldsm4(&b[jp * 4], sbB + swz(wn * 32 + jp * 16 + b_row0, c0 + b_cofs));
#pragma unroll
            for (int i = 0; i < 4; i++)
#pragma unroll
                for (int j = 0; j < 4; j++)
                    mma16816h(acc[i][j], a[i], &b[j * 2]);
        }
    }

    const int g = lane >> 2;
    const int tg = lane & 3;
    __syncthreads();

    if (z < 2) {
        float* red = (float*)smem;
        const int seg = wn >> 1;
        const int pr = wn & 1;

        float ml[4][2];
#pragma unroll
        for (int i = 0; i < 4; i++)
#pragma unroll
            for (int h = 0; h < 2; h++) {
                float m = acc[i][0][h * 2];
#pragma unroll
                for (int j = 0; j < 4; j++) {
                    m = fmaxf(m, acc[i][j][h * 2]);
                    m = fmaxf(m, acc[i][j][h * 2 + 1]);
                }
                m = fmaxf(m, __shfl_xor_sync(0xffffffffu, m, 1));
                m = fmaxf(m, __shfl_xor_sync(0xffffffffu, m, 2));
                ml[i][h] = m;
            }
        if (tg == 0) {
#pragma unroll
            for (int i = 0; i < 4; i++)
#pragma unroll
                for (int h = 0; h < 2; h++) {
                    int row = wm * 64 + i * 16 + h * 8 + g;
                    red[(row * 2 + seg) * 2 + pr] = ml[i][h];
                }
        }
        __syncthreads();
        float mseg[4][2];
#pragma unroll
        for (int i = 0; i < 4; i++)
#pragma unroll
            for (int h = 0; h < 2; h++) {
                int row = wm * 64 + i * 16 + h * 8 + g;
                mseg[i][h] = fmaxf(red[(row * 2 + seg) * 2 + 0],
                                   red[(row * 2 + seg) * 2 + 1]);
            }
        __syncthreads();

        float sl[4][2];
#pragma unroll
        for (int i = 0; i < 4; i++)
#pragma unroll
            for (int h = 0; h < 2; h++) {
                float s = 0.f;
#pragma unroll
                for (int j = 0; j < 4; j++) {
                    float e0 = __expf(acc[i][j][h * 2]     - mseg[i][h]);
                    float e1 = __expf(acc[i][j][h * 2 + 1] - mseg[i][h]);
                    acc[i][j][h * 2] = e0; acc[i][j][h * 2 + 1] = e1;
                    s += e0 + e1;
                }
                s += __shfl_xor_sync(0xffffffffu, s, 1);
                s += __shfl_xor_sync(0xffffffffu, s, 2);
                sl[i][h] = s;
            }
        if (tg == 0) {
#pragma unroll
            for (int i = 0; i < 4; i++)
#pragma unroll
                for (int h = 0; h < 2; h++) {
                    int row = wm * 64 + i * 16 + h * 8 + g;
                    red[(row * 2 + seg) * 2 + pr] = sl[i][h];
                }
        }
        __syncthreads();
#pragma unroll
        for (int i = 0; i < 4; i++)
#pragma unroll
            for (int h = 0; h < 2; h++) {
                int row = wm * 64 + i * 16 + h * 8 + g;
                float inv = 1.0f / (red[(row * 2 + seg) * 2 + 0] +
                                    red[(row * 2 + seg) * 2 + 1]);
#pragma unroll
                for (int j = 0; j < 4; j++) {
                    acc[i][j][h * 2]     *= inv;
                    acc[i][j][h * 2 + 1] *= inv;
                }
            }
    }

    // store fp16
#pragma unroll
    for (int i = 0; i < 4; i++) {
        const int r0 = m0 + wm * 64 + i * 16 + g;
#pragma unroll
        for (int j = 0; j < 4; j++) {
            const int cc = n0 + wn * 32 + j * 8 + tg * 2;
            *(__half2*)&Out[(size_t)r0 * DIM + cc] =
                __floats2half2_rn(acc[i][j][0], acc[i][j][1]);
            *(__half2*)&Out[(size_t)(r0 + 8) * DIM + cc] =
                __floats2half2_rn(acc[i][j][2], acc[i][j][3]);
        }
    }
}

// ---------------- per-chunk KV sums on HMMA: P = k^T v (64x64x128) ----------------
__global__ __launch_bounds__(256)
void chunk_kv()
{
    extern __shared__ char smem[];
    const uint32_t sb = smem_u32(smem);   // KH @0 (16KB), VH @16384 (16KB)

    const int c = blockIdx.x;
    const int nh = blockIdx.y;
    const int n = nh >> 4, h = nh & 15;
    const size_t base = ((size_t)(n * LSEQ + c * CHK)) * DIM + h * DH;
    const int tid = threadIdx.x;
    const int lane = tid & 31;
    const int wid = tid >> 5;

    {
        int lrow = tid >> 1, lc4 = (tid & 1) * 4;
        const __half* gk = g_Oh[1] + base + (size_t)lrow * DIM;
        const __half* gv = g_Oh[2] + base + (size_t)lrow * DIM;
#pragma unroll
        for (int c4 = 0; c4 < 4; c4++) {
            cp16(sb + swz(lrow, lc4 + c4), gk + (lc4 + c4) * 8);
            cp16(sb + 16384 + swz(lrow, lc4 + c4), gv + (lc4 + c4) * 8);
        }
    }
    CP_COMMIT(); CP_WAIT0(); __syncthreads();

    const int wmc = wid >> 1;    // d1 block (m16)
    const int wnc = wid & 1;     // d2 block (n32)
    const int ta_krow = ((lane >> 4) << 3) + (lane & 7);
    const int ta_mch  = (lane >> 3) & 1;
    const int tb_krow = (((lane >> 3) & 1) << 3) + (lane & 7);
    const int tb_nch  = lane >> 4;

    float acc[4][4];
#pragma unroll
    for (int j = 0; j < 4; j++)
#pragma unroll
        for (int r = 0; r < 4; r++) acc[j][r] = 0.f;

#pragma unroll
    for (int kt = 0; kt < 8; kt++) {
        const int t0 = kt * 16;
        uint32_t a[4], b[8];
        ldsm4t(a, sb + swz(t0 + ta_krow, 2 * wmc + ta_mch));
#pragma unroll
        for (int jp = 0; jp < 2; jp++)
            ldsm4t(&b[jp * 4], sb + 16384 + swz(t0 + tb_krow, 4 * wnc + 2 * jp + tb_nch));
#pragma unroll
        for (int j = 0; j < 4; j++)
            mma16816h(acc[j], a, &b[j * 2]);
    }

    const int g = lane >> 2, tg = lane & 3;
    __half* P = g_Ph + ((size_t)nh * NCHK + c) * (DH * DH);
#pragma unroll
    for (int j = 0; j < 4; j++) {
        int row = 16 * wmc + g;
        int col = 32 * wnc + 8 * j + 2 * tg;
        *(__half2*)&P[row * 64 + col] = __floats2half2_rn(acc[j][0], acc[j][1]);
        *(__half2*)&P[(row + 8) * 64 + col] = __floats2half2_rn(acc[j][2], acc[j][3]);
    }
}

// ---------------- exclusive prefix: batched loads (MLP=16), reg scan ----------------
// grid: (NB*NH) * 8 slabs of 256; one half2 lane per thread.
__global__ __launch_bounds__(256)
void prefix_kv()
{
    const int nh = blockIdx.x >> 3;
    const int slab = blockIdx.x & 7;
    const __half2* __restrict__ P = (const __half2*)(g_Ph + (size_t)nh * NCHK * (DH * DH));
    __half2* __restrict__ S = (__half2*)(g_Sh + (size_t)nh * NCHK * (DH * DH));
    const int idx = slab * 256 + threadIdx.x;   // 0..2047 half2 lanes

    __half2 v[NCHK];
#pragma unroll
    for (int c = 0; c < NCHK; c++) v[c] = P[c * 2048 + idx];   // independent loads

    float rx = 0.f, ry = 0.f;
#pragma unroll
    for (int c = 0; c < NCHK; c++) {
        float2 t = __half22float2(v[c]);
        v[c] = __floats2half2_rn(rx, ry);
        rx += t.x; ry += t.y;
    }
#pragma unroll
    for (int c = 0; c < NCHK; c++) S[c * 2048 + idx] = v[c];   // independent stores
}

// ---------------- attention output on HMMA ----------------
// smem: QH 16K @0, KH 16K @16384, VH 16K @32768, SH 8K @49152, AH 32K @57344
#define AT_QH 0
#define AT_KH 16384
#define AT_VH 32768
#define AT_SH 49152
#define AT_AH 57344
#define AT_BYTES (AT_AH + 32768)   // 90112

__global__ __launch_bounds__(256, 2)
void attn_out(float* __restrict__ out)
{
    extern __shared__ char smem[];
    const uint32_t sb = smem_u32(smem);

    const int c = blockIdx.x;
    const int nh = blockIdx.y;
    const int n = nh >> 4, h = nh & 15;
    const size_t base = ((size_t)(n * LSEQ + c * CHK)) * DIM + h * DH;
    const int tid = threadIdx.x;
    const int lane = tid & 31;
    const int wid = tid >> 5;
    const int g = lane >> 2, tg = lane & 3;

    const int a_row = (lane & 7) + ((lane >> 3) & 1) * 8;
    const int a_cofs = lane >> 4;
    const int b_row0 = ((lane >> 4) & 1) * 8 + (lane & 7);
    const int b_cofs = (lane >> 3) & 1;
    const int tb_krow = (((lane >> 3) & 1) << 3) + (lane & 7);
    const int tb_nch  = lane >> 4;

    // ---- load QH/KH/VH (128 rows) + SH (64 rows, only if c>0) ----
    {
        int lrow = tid >> 1, lc4 = (tid & 1) * 4;
        const __half* gq = g_Oh[0] + base + (size_t)lrow * DIM;
        const __half* gk = g_Oh[1] + base + (size_t)lrow * DIM;
        const __half* gv = g_Oh[2] + base + (size_t)lrow * DIM;
#pragma unroll
        for (int c4 = 0; c4 < 4; c4++) {
            int ch = lc4 + c4;
            cp16(sb + AT_QH + swz(lrow, ch), gq + ch * 8);
            cp16(sb + AT_KH + swz(lrow, ch), gk + ch * 8);
            cp16(sb + AT_VH + swz(lrow, ch), gv + ch * 8);
        }
        if (c > 0 && tid < 128) {
            const __half* gs = g_Sh + ((size_t)nh * NCHK + c) * (DH * DH) + lrow * 64;
#pragma unroll
            for (int c4 = 0; c4 < 4; c4++) {
                int ch = lc4 + c4;
                cp16(sb + AT_SH + swz(lrow, ch), gs + ch * 8);
            }
        }
    }
    CP_COMMIT(); CP_WAIT0(); __syncthreads();

    // ---- stage 1: A = causal(q k^T) -> AH fp16 ----
    {
        const int wm1 = wid >> 2, wn1 = wid & 3;
        if (wm1 == 0 && wn1 >= 2) {
            int row = (wn1 - 2) * 32 + lane;
            uint4 zz = make_uint4(0, 0, 0, 0);
#pragma unroll
            for (int cc8 = 0; cc8 < 8; cc8++)
                *(uint4*)(smem + AT_AH + row * 256 + 128 + cc8 * 16) = zz;
        } else {
            float acc1[4][4][4];
#pragma unroll
            for (int i = 0; i < 4; i++)
#pragma unroll
                for (int j = 0; j < 4; j++)
#pragma unroll
                    for (int r = 0; r < 4; r++) acc1[i][j][r] = 0.f;

#pragma unroll
            for (int ks = 0; ks < 4; ks++) {
                const int c0 = ks * 2;
                uint32_t a[4][4], b[8];
#pragma unroll
                for (int i = 0; i < 4; i++)
                    ldsm4(a[i], sb + AT_QH + swz(64 * wm1 + 16 * i + a_row, c0 + a_cofs));
#pragma unroll
                for (int jp = 0; jp < 2; jp++)
                    ldsm4(&b[jp * 4], sb + AT_KH + swz(32 * wn1 + 16 * jp + b_row0, c0 + b_cofs));
#pragma unroll
                for (int i = 0; i < 4; i++)
#pragma unroll
                    for (int j = 0; j < 4; j++)
                        mma16816h(acc1[i][j], a[i], &b[j * 2]);
            }
#pragma unroll
            for (int i = 0; i < 4; i++) {
                int r0 = 64 * wm1 + 16 * i + g;
#pragma unroll
                for (int j = 0; j < 4; j++) {
                    int cb = 32 * wn1 + 8 * j + 2 * tg;
                    int ch = cb >> 3;
                    float v0 = (cb     <= r0) ? acc1[i][j][0] : 0.f;
                    float v1 = (cb + 1 <= r0) ? acc1[i][j][1] : 0.f;
                    *(__half2*)(smem + AT_AH + swzA(r0, ch) + (cb & 7) * 2) =
                        __floats2half2_rn(v0, v1);
                    int r1 = r0 + 8;
                    float v2 = (cb     <= r1) ? acc1[i][j][2] : 0.f;
                    float v3 = (cb + 1 <= r1) ? acc1[i][j][3] : 0.f;
                    *(__half2*)(smem + AT_AH + swzA(r1, ch) + (cb & 7) * 2) =
                        __floats2half2_rn(v2, v3);
                }
            }
        }
    }
    __syncthreads();

    // ---- stage 2: o = q @ S_excl + A @ v ----
    const int wm2 = wid >> 1;
    const int wn2 = wid & 1;
    float o2[2][4][4];
#pragma unroll
    for (int i = 0; i < 2; i++)
#pragma unroll
        for (int j = 0; j < 4; j++)
#pragma unroll
            for (int r = 0; r < 4; r++) o2[i][j][r] = 0.f;

    if (c > 0) {
#pragma unroll
        for (int ks = 0; ks < 4; ks++) {
            const int c0 = ks * 2, d0 = ks * 16;
            uint32_t a[2][4], b[8];
#pragma unroll
            for (int i = 0; i < 2; i++)
                ldsm4(a[i], sb + AT_QH + swz(32 * wm2 + 16 * i + a_row, c0 + a_cofs));
#pragma unroll
            for (int jp = 0; jp < 2; jp++)
                ldsm4t(&b[jp * 4], sb + AT_SH + swz(d0 + tb_krow, 4 * wn2 + 2 * jp + tb_nch));
#pragma unroll
            for (int i = 0; i < 2; i++)
#pragma unroll
                for (int j = 0; j < 4; j++)
                    mma16816h(o2[i][j], a[i], &b[j * 2]);
        }
    }
    const int nkt = 2 * (wm2 + 1);
    for (int kt = 0; kt < nkt; kt++) {
        const int s0 = kt * 16;
        uint32_t a[2][4], b[8];
#pragma unroll
        for (int i = 0; i < 2; i++)
            ldsm4(a[i], sb + AT_AH + swzA(32 * wm2 + 16 * i + a_row, 2 * kt + a_cofs));
#pragma unroll
        for (int jp = 0; jp < 2; jp++)
            ldsm4t(&b[jp * 4], sb + AT_VH + swz(s0 + tb_krow, 4 * wn2 + 2 * jp + tb_nch));
#pragma unroll
        for (int i = 0; i < 2; i++)
#pragma unroll
            for (int j = 0; j < 4; j++)
                mma16816h(o2[i][j], a[i], &b[j * 2]);
    }

#pragma unroll
    for (int i = 0; i < 2; i++) {
        int row = 32 * wm2 + 16 * i + g;
#pragma unroll
        for (int j = 0; j < 4; j++) {
            int col = 32 * wn2 + 8 * j + 2 * tg;
            *(float2*)&out[base + (size_t)row * DIM + col] =
                make_float2(o2[i][j][0], o2[i][j][1]);
            *(float2*)&out[base + (size_t)(row + 8) * DIM + col] =
                make_float2(o2[i][j][2], o2[i][j][3]);
        }
    }
}

// ---------------------------------------------------------------------------
extern "C" void kernel_launch(void* const* d_in, const int* in_sizes, int n_in,
                              void* d_out, int out_size)
{
    const float* query = (const float*)d_in[0];
    const float* key   = (const float*)d_in[1];
    const float* Wq    = (const float*)d_in[2];
    const float* Wk    = (const float*)d_in[3];
    const float* Wv    = (const float*)d_in[4];
    float* out = (float*)d_out;

    cudaFuncSetAttribute(proj_hmma, cudaFuncAttributeMaxDynamicSharedMemorySize, SMEM_TOTAL);
    cudaFuncSetAttribute(chunk_kv, cudaFuncAttributeMaxDynamicSharedMemorySize, 32768);
    cudaFuncSetAttribute(attn_out, cudaFuncAttributeMaxDynamicSharedMemorySize, AT_BYTES);

    // 1. fp16 conversion
    conv_split<<<dim3(384, 5), 256>>>(query, key, Wq, Wk, Wv);

    // 2. projections (fp16 HMMA, fused softmax, fp16 output)
    proj_hmma<<<dim3(8, 32, 3), 256, SMEM_TOTAL>>>();

    // 3. chunked causal linear attention, all on HMMA
    dim3 agrid(NCHK, NBATCH * NH);
    chunk_kv<<<agrid, 256, 32768>>>();
    prefix_kv<<<NBATCH * NH * 8, 256>>>();
    attn_out<<<agrid, 256, AT_BYTES>>>(out);
}

// round 16
// speedup vs baseline: 3.8516x; 1.0321x over previous
#include <cuda_runtime.h>
#include <cuda_fp16.h>
#include <cstdint>
#include <cstddef>

// ---------------- problem constants ----------------
#define NBATCH 2
#define LSEQ   2048
#define DIM    1024
#define NH     16
#define DH     64
#define CHK    128
#define NCHK   (LSEQ / CHK)      // 16
#define MROWS  (NBATCH * LSEQ)   // 4096

// ---------------- device scratch (no allocs allowed) ----------------
__device__ __align__(16) __half g_Xh[2][MROWS * DIM];    // fp16 inputs (q,k)
__device__ __align__(16) __half g_Wh[3][DIM * DIM];      // fp16 weights
__device__ __align__(16) __half g_Oh[3][MROWS * DIM];    // fp16 projected Q,K,V
__device__ __align__(16) __half g_Ph[NBATCH * NH * NCHK * DH * DH];  // chunk sums fp16
__device__ __align__(16) __half g_Sh[NBATCH * NH * NCHK * DH * DH];  // excl prefix fp16

// ---------------- small helpers ----------------
__device__ __forceinline__ uint32_t smem_u32(const void* p) {
    uint32_t a;
    asm("{ .reg .u64 t; cvta.to.shared.u64 t, %1; cvt.u32.u64 %0, t; }" : "=r"(a) : "l"(p));
    return a;
}
__device__ __forceinline__ void cp16(uint32_t s, const void* g) {
    asm volatile("cp.async.cg.shared.global [%0], [%1], 16;" :: "r"(s), "l"(g));
}
#define CP_COMMIT() asm volatile("cp.async.commit_group;" ::: "memory")
#define CP_WAIT1()  asm volatile("cp.async.wait_group 1;" ::: "memory")
#define CP_WAIT0()  asm volatile("cp.async.wait_group 0;" ::: "memory")

__device__ __forceinline__ void mma16816h(float* c, const uint32_t* a, const uint32_t* b) {
    asm volatile(
        "mma.sync.aligned.m16n8k16.row.col.f32.f16.f16.f32 "
        "{%0,%1,%2,%3}, {%4,%5,%6,%7}, {%8,%9}, {%0,%1,%2,%3};"
        : "+f"(c[0]), "+f"(c[1]), "+f"(c[2]), "+f"(c[3])
        : "r"(a[0]), "r"(a[1]), "r"(a[2]), "r"(a[3]), "r"(b[0]), "r"(b[1]));
}
__device__ __forceinline__ void ldsm4(uint32_t* r, uint32_t addr) {
    asm volatile("ldmatrix.sync.aligned.m8n8.x4.shared.b16 {%0,%1,%2,%3}, [%4];"
                 : "=r"(r[0]), "=r"(r[1]), "=r"(r[2]), "=r"(r[3]) : "r"(addr));
}
__device__ __forceinline__ void ldsm4t(uint32_t* r, uint32_t addr) {
    asm volatile("ldmatrix.sync.aligned.m8n8.x4.trans.shared.b16 {%0,%1,%2,%3}, [%4];"
                 : "=r"(r[0]), "=r"(r[1]), "=r"(r[2]), "=r"(r[3]) : "r"(addr));
}

// swizzled byte offset: 128B-pitch rows, 16B chunk c (0..7)
__device__ __forceinline__ uint32_t swz(int row, int c) {
    return (uint32_t)(row * 128 + ((c ^ (row & 7)) << 4));
}
// 256B-pitch rows, 16 chunks: XOR low 3 bits only
__device__ __forceinline__ uint32_t swzA(int row, int c) {
    return (uint32_t)(row * 256 + (((c & 8) | ((c & 7) ^ (row & 7))) << 4));
}

// ---------------- fp16 conversion ----------------
__global__ __launch_bounds__(256)
void conv_split(const float* __restrict__ q, const float* __restrict__ k,
                const float* __restrict__ wq, const float* __restrict__ wk,
                const float* __restrict__ wv)
{
    int y = blockIdx.y;
    const float* src;
    __half* dst;
    int n;
    switch (y) {
        case 0: src = q;  dst = g_Xh[0]; n = MROWS * DIM; break;
        case 1: src = k;  dst = g_Xh[1]; n = MROWS * DIM; break;
        case 2: src = wq; dst = g_Wh[0]; n = DIM * DIM;   break;
        case 3: src = wk; dst = g_Wh[1]; n = DIM * DIM;   break;
        default: src = wv; dst = g_Wh[2]; n = DIM * DIM;  break;
    }
    int n4 = n >> 2;
    for (int i = blockIdx.x * blockDim.x + threadIdx.x; i < n4;
         i += gridDim.x * blockDim.x) {
        float4 f = ((const float4*)src)[i];
        ushort4 u = make_ushort4(
            __half_as_ushort(__float2half(f.x)), __half_as_ushort(__float2half(f.y)),
            __half_as_ushort(__float2half(f.z)), __half_as_ushort(__float2half(f.w)));
        ((ushort4*)dst)[i] = u;
    }
}

// ---------------- HMMA projection GEMM (+ fused intra-warp softmax) ----------------
// 128x128 CTA tile, BK=64 (16 iters), 8 warps of 32x64 (4x2 grid), ldmatrix.x4,
// XOR-swizzled 128B rows, 3-stage cp.async ring. Each warp owns a full 64-col
// head segment -> softmax is intra-warp (shfl over tg only), zero barriers.
#define STAGE_BYTES 32768
#define SMEM_TOTAL  (3 * STAGE_BYTES)

__global__ __launch_bounds__(256, 2)
void proj_hmma()
{
    extern __shared__ char smem[];
    const uint32_t sb = smem_u32(smem);

    const int tid = threadIdx.x;
    const int wid = tid >> 5;
    const int lane = tid & 31;
    const int wm = wid >> 1;       // 0..3 (32-row block)
    const int wn = wid & 1;        // 0..1 (64-col block = head segment)
    const int z = blockIdx.z;

    const __half* __restrict__ A = g_Xh[z ? 1 : 0];
    const __half* __restrict__ B = g_Wh[z];
    __half* __restrict__ Out = g_Oh[z];

    const int m0 = blockIdx.y * 128;
    const int n0 = blockIdx.x * 128;

    float acc[2][8][4];
#pragma unroll
    for (int i = 0; i < 2; i++)
#pragma unroll
        for (int j = 0; j < 8; j++)
#pragma unroll
            for (int r = 0; r < 4; r++) acc[i][j][r] = 0.f;

    const int lrow = tid >> 1;
    const int lc4  = (tid & 1) * 4;
    auto load_tile = [&](int kk, int stg) {
        const int k0 = kk * 64;
        const uint32_t sa = sb + stg * STAGE_BYTES;
        const uint32_t sbB = sa + 16384;
        const __half* ga = A + (size_t)(m0 + lrow) * DIM + k0 + lc4 * 8;
        const __half* gb = B + (size_t)(n0 + lrow) * DIM + k0 + lc4 * 8;
#pragma unroll
        for (int c = 0; c < 4; c++) {
            cp16(sa  + swz(lrow, lc4 + c), ga + c * 8);
            cp16(sbB + swz(lrow, lc4 + c), gb + c * 8);
        }
    };

    const int a_row = (lane & 7) + ((lane >> 3) & 1) * 8;
    const int a_cofs = lane >> 4;
    const int b_row0 = ((lane >> 4) & 1) * 8 + (lane & 7);
    const int b_cofs = (lane >> 3) & 1;

    load_tile(0, 0); CP_COMMIT();
    load_tile(1, 1); CP_COMMIT();

    for (int kk = 0; kk < 16; kk++) {
        const int stg = kk % 3;
        CP_WAIT1();
        __syncthreads();
        if (kk + 2 < 16) { load_tile(kk + 2, (kk + 2) % 3); CP_COMMIT(); }

        const uint32_t sa = sb + stg * STAGE_BYTES;
        const uint32_t sbB = sa + 16384;

#pragma unroll
        for (int ks = 0; ks < 4; ks++) {
            const int c0 = ks * 2;
            uint32_t a[2][4], b[16];
#pragma unroll
            for (int i = 0; i < 2; i++)
                ldsm4(a[i], sa + swz(wm * 32 + i * 16 + a_row, c0 + a_cofs));
#pragma unroll
            for (int jp = 0; jp < 4; jp++)
                ldsm4(&b[jp * 4], sbB + swz(wn * 64 + jp * 16 + b_row0, c0 + b_cofs));
#pragma unroll
            for (int i = 0; i < 2; i++)
#pragma unroll
                for (int j = 0; j < 8; j++)
                    mma16816h(acc[i][j], a[i], &b[j * 2]);
        }
    }

    const int g = lane >> 2;
    const int tg = lane & 3;

    if (z < 2) {
        // intra-warp softmax over this warp's 64-col head segment
#pragma unroll
        for (int i = 0; i < 2; i++)
#pragma unroll
            for (int h = 0; h < 2; h++) {
                float m = acc[i][0][h * 2];
#pragma unroll
                for (int j = 0; j < 8; j++) {
                    m = fmaxf(m, acc[i][j][h * 2]);
                    m = fmaxf(m, acc[i][j][h * 2 + 1]);
                }
                m = fmaxf(m, __shfl_xor_sync(0xffffffffu, m, 1));
                m = fmaxf(m, __shfl_xor_sync(0xffffffffu, m, 2));
                float s = 0.f;
#pragma unroll
                for (int j = 0; j < 8; j++) {
                    float e0 = __expf(acc[i][j][h * 2]     - m);
                    float e1 = __expf(acc[i][j][h * 2 + 1] - m);
                    acc[i][j][h * 2] = e0; acc[i][j][h * 2 + 1] = e1;
                    s += e0 + e1;
                }
                s += __shfl_xor_sync(0xffffffffu, s, 1);
                s += __shfl_xor_sync(0xffffffffu, s, 2);
                float inv = 1.0f / s;
#pragma unroll
                for (int j = 0; j < 8; j++) {
                    acc[i][j][h * 2]     *= inv;
                    acc[i][j][h * 2 + 1] *= inv;
                }
            }
    }

    // store fp16
#pragma unroll
    for (int i = 0; i < 2; i++) {
        const int r0 = m0 + wm * 32 + i * 16 + g;
#pragma unroll
        for (int j = 0; j < 8; j++) {
            const int cc = n0 + wn * 64 + j * 8 + tg * 2;
            *(__half2*)&Out[(size_t)r0 * DIM + cc] =
                __floats2half2_rn(acc[i][j][0], acc[i][j][1]);
            *(__half2*)&Out[(size_t)(r0 + 8) * DIM + cc] =
                __floats2half2_rn(acc[i][j][2], acc[i][j][3]);
        }
    }
}

// ---------------- per-chunk KV sums on HMMA: P = k^T v (64x64x128) ----------------
__global__ __launch_bounds__(256)
void chunk_kv()
{
    extern __shared__ char smem[];
    const uint32_t sb = smem_u32(smem);   // KH @0 (16KB), VH @16384 (16KB)

    const int c = blockIdx.x;
    const int nh = blockIdx.y;
    const int n = nh >> 4, h = nh & 15;
    const size_t base = ((size_t)(n * LSEQ + c * CHK)) * DIM + h * DH;
    const int tid = threadIdx.x;
    const int lane = tid & 31;
    const int wid = tid >> 5;

    {
        int lrow = tid >> 1, lc4 = (tid & 1) * 4;
        const __half* gk = g_Oh[1] + base + (size_t)lrow * DIM;
        const __half* gv = g_Oh[2] + base + (size_t)lrow * DIM;
#pragma unroll
        for (int c4 = 0; c4 < 4; c4++) {
            cp16(sb + swz(lrow, lc4 + c4), gk + (lc4 + c4) * 8);
            cp16(sb + 16384 + swz(lrow, lc4 + c4), gv + (lc4 + c4) * 8);
        }
    }
    CP_COMMIT(); CP_WAIT0(); __syncthreads();

    const int wmc = wid >> 1;
    const int wnc = wid & 1;
    const int ta_krow = ((lane >> 4) << 3) + (lane & 7);
    const int ta_mch  = (lane >> 3) & 1;
    const int tb_krow = (((lane >> 3) & 1) << 3) + (lane & 7);
    const int tb_nch  = lane >> 4;

    float acc[4][4];
#pragma unroll
    for (int j = 0; j < 4; j++)
#pragma unroll
        for (int r = 0; r < 4; r++) acc[j][r] = 0.f;

#pragma unroll
    for (int kt = 0; kt < 8; kt++) {
        const int t0 = kt * 16;
        uint32_t a[4], b[8];
        ldsm4t(a, sb + swz(t0 + ta_krow, 2 * wmc + ta_mch));
#pragma unroll
        for (int jp = 0; jp < 2; jp++)
            ldsm4t(&b[jp * 4], sb + 16384 + swz(t0 + tb_krow, 4 * wnc + 2 * jp + tb_nch));
#pragma unroll
        for (int j = 0; j < 4; j++)
            mma16816h(acc[j], a, &b[j * 2]);
    }

    const int g = lane >> 2, tg = lane & 3;
    __half* P = g_Ph + ((size_t)nh * NCHK + c) * (DH * DH);
#pragma unroll
    for (int j = 0; j < 4; j++) {
        int row = 16 * wmc + g;
        int col = 32 * wnc + 8 * j + 2 * tg;
        *(__half2*)&P[row * 64 + col] = __floats2half2_rn(acc[j][0], acc[j][1]);
        *(__half2*)&P[(row + 8) * 64 + col] = __floats2half2_rn(acc[j][2], acc[j][3]);
    }
}

// ---------------- exclusive prefix: batched loads (MLP=16), reg scan ----------------
__global__ __launch_bounds__(256)
void prefix_kv()
{
    const int nh = blockIdx.x >> 3;
    const int slab = blockIdx.x & 7;
    const __half2* __restrict__ P = (const __half2*)(g_Ph + (size_t)nh * NCHK * (DH * DH));
    __half2* __restrict__ S = (__half2*)(g_Sh + (size_t)nh * NCHK * (DH * DH));
    const int idx = slab * 256 + threadIdx.x;

    __half2 v[NCHK];
#pragma unroll
    for (int c = 0; c < NCHK; c++) v[c] = P[c * 2048 + idx];

    float rx = 0.f, ry = 0.f;
#pragma unroll
    for (int c = 0; c < NCHK; c++) {
        float2 t = __half22float2(v[c]);
        v[c] = __floats2half2_rn(rx, ry);
        rx += t.x; ry += t.y;
    }
#pragma unroll
    for (int c = 0; c < NCHK; c++) S[c * 2048 + idx] = v[c];
}

// ---------------- attention output on HMMA ----------------
#define AT_QH 0
#define AT_KH 16384
#define AT_VH 32768
#define AT_SH 49152
#define AT_AH 57344
#define AT_BYTES (AT_AH + 32768)   // 90112

__global__ __launch_bounds__(256, 2)
void attn_out(float* __restrict__ out)
{
    extern __shared__ char smem[];
    const uint32_t sb = smem_u32(smem);

    const int c = blockIdx.x;
    const int nh = blockIdx.y;
    const int n = nh >> 4, h = nh & 15;
    const size_t base = ((size_t)(n * LSEQ + c * CHK)) * DIM + h * DH;
    const int tid = threadIdx.x;
    const int lane = tid & 31;
    const int wid = tid >> 5;
    const int g = lane >> 2, tg = lane & 3;

    const int a_row = (lane & 7) + ((lane >> 3) & 1) * 8;
    const int a_cofs = lane >> 4;
    const int b_row0 = ((lane >> 4) & 1) * 8 + (lane & 7);
    const int b_cofs = (lane >> 3) & 1;
    const int tb_krow = (((lane >> 3) & 1) << 3) + (lane & 7);
    const int tb_nch  = lane >> 4;

    {
        int lrow = tid >> 1, lc4 = (tid & 1) * 4;
        const __half* gq = g_Oh[0] + base + (size_t)lrow * DIM;
        const __half* gk = g_Oh[1] + base + (size_t)lrow * DIM;
        const __half* gv = g_Oh[2] + base + (size_t)lrow * DIM;
#pragma unroll
        for (int c4 = 0; c4 < 4; c4++) {
            int ch = lc4 + c4;
            cp16(sb + AT_QH + swz(lrow, ch), gq + ch * 8);
            cp16(sb + AT_KH + swz(lrow, ch), gk + ch * 8);
            cp16(sb + AT_VH + swz(lrow, ch), gv + ch * 8);
        }
        if (c > 0 && tid < 128) {
            const __half* gs = g_Sh + ((size_t)nh * NCHK + c) * (DH * DH) + lrow * 64;
#pragma unroll
            for (int c4 = 0; c4 < 4; c4++) {
                int ch = lc4 + c4;
                cp16(sb + AT_SH + swz(lrow, ch), gs + ch * 8);
            }
        }
    }
    CP_COMMIT(); CP_WAIT0(); __syncthreads();

    // stage 1: A = causal(q k^T) -> AH fp16
    {
        const int wm1 = wid >> 2, wn1 = wid & 3;
        if (wm1 == 0 && wn1 >= 2) {
            int row = (wn1 - 2) * 32 + lane;
            uint4 zz = make_uint4(0, 0, 0, 0);
#pragma unroll
            for (int cc8 = 0; cc8 < 8; cc8++)
                *(uint4*)(smem + AT_AH + row * 256 + 128 + cc8 * 16) = zz;
        } else {
            float acc1[4][4][4];
#pragma unroll
            for (int i = 0; i < 4; i++)
#pragma unroll
                for (int j = 0; j < 4; j++)
#pragma unroll
                    for (int r = 0; r < 4; r++) acc1[i][j][r] = 0.f;

#pragma unroll
            for (int ks = 0; ks < 4; ks++) {
                const int c0 = ks * 2;
                uint32_t a[4][4], b[8];
#pragma unroll
                for (int i = 0; i < 4; i++)
                    ldsm4(a[i], sb + AT_QH + swz(64 * wm1 + 16 * i + a_row, c0 + a_cofs));
#pragma unroll
                for (int jp = 0; jp < 2; jp++)
                    ldsm4(&b[jp * 4], sb + AT_KH + swz(32 * wn1 + 16 * jp + b_row0, c0 + b_cofs));
#pragma unroll
                for (int i = 0; i < 4; i++)
#pragma unroll
                    for (int j = 0; j < 4; j++)
                        mma16816h(acc1[i][j], a[i], &b[j * 2]);
            }
#pragma unroll
            for (int i = 0; i < 4; i++) {
                int r0 = 64 * wm1 + 16 * i + g;
#pragma unroll
                for (int j = 0; j < 4; j++) {
                    int cb = 32 * wn1 + 8 * j + 2 * tg;
                    int ch = cb >> 3;
                    float v0 = (cb     <= r0) ? acc1[i][j][0] : 0.f;
                    float v1 = (cb + 1 <= r0) ? acc1[i][j][1] : 0.f;
                    *(__half2*)(smem + AT_AH + swzA(r0, ch) + (cb & 7) * 2) =
                        __floats2half2_rn(v0, v1);
                    int r1 = r0 + 8;
                    float v2 = (cb     <= r1) ? acc1[i][j][2] : 0.f;
                    float v3 = (cb + 1 <= r1) ? acc1[i][j][3] : 0.f;
                    *(__half2*)(smem + AT_AH + swzA(r1, ch) + (cb & 7) * 2) =
                        __floats2half2_rn(v2, v3);
                }
            }
        }
    }
    __syncthreads();

    // stage 2: o = q @ S_excl + A @ v
    const int wm2 = wid >> 1;
    const int wn2 = wid & 1;
    float o2[2][4][4];
#pragma unroll
    for (int i = 0; i < 2; i++)
#pragma unroll
        for (int j = 0; j < 4; j++)
#pragma unroll
            for (int r = 0; r < 4; r++) o2[i][j][r] = 0.f;

    if (c > 0) {
#pragma unroll
        for (int ks = 0; ks < 4; ks++) {
            const int c0 = ks * 2, d0 = ks * 16;
            uint32_t a[2][4], b[8];
#pragma unroll
            for (int i = 0; i < 2; i++)
                ldsm4(a[i], sb + AT_QH + swz(32 * wm2 + 16 * i + a_row, c0 + a_cofs));
#pragma unroll
            for (int jp = 0; jp < 2; jp++)
                ldsm4t(&b[jp * 4], sb + AT_SH + swz(d0 + tb_krow, 4 * wn2 + 2 * jp + tb_nch));
#pragma unroll
            for (int i = 0; i < 2; i++)
#pragma unroll
                for (int j = 0; j < 4; j++)
                    mma16816h(o2[i][j], a[i], &b[j * 2]);
        }
    }
    const int nkt = 2 * (wm2 + 1);
    for (int kt = 0; kt < nkt; kt++) {
        const int s0 = kt * 16;
        uint32_t a[2][4], b[8];
#pragma unroll
        for (int i = 0; i < 2; i++)
            ldsm4(a[i], sb + AT_AH + swzA(32 * wm2 + 16 * i + a_row, 2 * kt + a_cofs));
#pragma unroll
        for (int jp = 0; jp < 2; jp++)
            ldsm4t(&b[jp * 4], sb + AT_VH + swz(s0 + tb_krow, 4 * wn2 + 2 * jp + tb_nch));
#pragma unroll
        for (int i = 0; i < 2; i++)
#pragma unroll
            for (int j = 0; j < 4; j++)
                mma16816h(o2[i][j], a[i], &b[j * 2]);
    }

#pragma unroll
    for (int i = 0; i < 2; i++) {
        int row = 32 * wm2 + 16 * i + g;
#pragma unroll
        for (int j = 0; j < 4; j++) {
            int col = 32 * wn2 + 8 * j + 2 * tg;
            *(float2*)&out[base + (size_t)row * DIM + col] =
                make_float2(o2[i][j][0], o2[i][j][1]);
            *(float2*)&out[base + (size_t)(row + 8) * DIM + col] =
                make_float2(o2[i][j][2], o2[i][j][3]);
        }
    }
}

// ---------------------------------------------------------------------------
extern "C" void kernel_launch(void* const* d_in, const int* in_sizes, int n_in,
                              void* d_out, int out_size)
{
    const float* query = (const float*)d_in[0];
    const float* key   = (const float*)d_in[1];
    const float* Wq    = (const float*)d_in[2];
    const float* Wk    = (const float*)d_in[3];
    const float* Wv    = (const float*)d_in[4];
    float* out = (float*)d_out;

    cudaFuncSetAttribute(proj_hmma, cudaFuncAttributeMaxDynamicSharedMemorySize, SMEM_TOTAL);
    cudaFuncSetAttribute(chunk_kv, cudaFuncAttributeMaxDynamicSharedMemorySize, 32768);
    cudaFuncSetAttribute(attn_out, cudaFuncAttributeMaxDynamicSharedMemorySize, AT_BYTES);

    // 1. fp16 conversion
    conv_split<<<dim3(384, 5), 256>>>(query, key, Wq, Wk, Wv);

    // 2. projections (fp16 HMMA, fused intra-warp softmax, fp16 output)
    proj_hmma<<<dim3(8, 32, 3), 256, SMEM_TOTAL>>>();

    // 3. chunked causal linear attention, all on HMMA
    dim3 agrid(NCHK, NBATCH * NH);
    chunk_kv<<<agrid, 256, 32768>>>();
    prefix_kv<<<NBATCH * NH * 8, 256>>>();
    attn_out<<<agrid, 256, AT_BYTES>>>(out);
}